// round 5
// baseline (speedup 1.0000x reference)
#include <cuda_runtime.h>
#include <cuda_bf16.h>
#include <math.h>
#include <stdint.h>

#define MT 16384   // B*T rows
#define DD 768     // embed dim

// ---- GEMM tiling ----
#define BK 32
#define NC (DD / BK)       // 24
#define PADK 40
#define TILE_SM (128 * PADK * 2)
#define STAGE_SM (4 * TILE_SM)

// ---- attention tiling ----
#define TQ 32
#define JW 288
#define SSTR 296           // padded S row (bf16 elems)
#define VSTR 264           // padded V row (bf16 elems)
// smem layout (bytes)
#define S_H_OFF 0
#define S_L_OFF 18944
#define A_OFF   37888
#define P1_STAGE 51200
#define P1_KH 0
#define P1_KL 23040
#define P1_QH 46080
#define P1_QL 48640
#define P2_STAGE 33792
#define P2_VH 0
#define P2_VL 16896
#define Y_OFF  105472      // A_OFF + 2*P2_STAGE
#define ATTN_SMEM 203776   // Y_OFF + 32*768*4

// 1/sqrt(768*256)
#define INV_SCALE 0.0022552744890219756f

// ---------------------------------------------------------------------------
// scratch
// ---------------------------------------------------------------------------
__device__ __nv_bfloat16 g_Xh[MT * DD];
__device__ __nv_bfloat16 g_Xl[MT * DD];
__device__ __nv_bfloat16 g_Hh[MT * DD];
__device__ __nv_bfloat16 g_Hl[MT * DD];
__device__ __nv_bfloat16 g_Wth[DD * DD];
__device__ __nv_bfloat16 g_Wtl[DD * DD];
__device__ __nv_bfloat16 g_Qh[MT * DD];
__device__ __nv_bfloat16 g_Ql[MT * DD];
__device__ __nv_bfloat16 g_Kh[MT * DD];
__device__ __nv_bfloat16 g_Kl[MT * DD];
__device__ __nv_bfloat16 g_Vh[MT * DD];
__device__ __nv_bfloat16 g_Vl[MT * DD];

__device__ __forceinline__ float gelu_exact(float x) {
    return 0.5f * x * (1.0f + erff(x * 0.70710678118654752f));
}

__device__ __forceinline__ uint32_t s2u(const void* p) {
    uint32_t a;
    asm("{ .reg .u64 t; cvta.to.shared.u64 t, %1; cvt.u32.u64 %0, t; }"
        : "=r"(a) : "l"(p));
    return a;
}

// ---- tensor-core primitives (compute_80 features) ----
__device__ __forceinline__ void mma_bf16(float* c, const uint32_t* a, const uint32_t* b) {
    asm volatile(
        "mma.sync.aligned.m16n8k16.row.col.f32.bf16.bf16.f32 "
        "{%0,%1,%2,%3}, {%4,%5,%6,%7}, {%8,%9}, {%0,%1,%2,%3};"
        : "+f"(c[0]), "+f"(c[1]), "+f"(c[2]), "+f"(c[3])
        : "r"(a[0]), "r"(a[1]), "r"(a[2]), "r"(a[3]), "r"(b[0]), "r"(b[1]));
}
__device__ __forceinline__ void ldsm_x4(uint32_t* r, uint32_t addr) {
    asm volatile("ldmatrix.sync.aligned.m8n8.x4.shared.b16 {%0,%1,%2,%3}, [%4];"
                 : "=r"(r[0]), "=r"(r[1]), "=r"(r[2]), "=r"(r[3]) : "r"(addr));
}
__device__ __forceinline__ void ldsm_x4_t(uint32_t* r, uint32_t addr) {
    asm volatile("ldmatrix.sync.aligned.m8n8.x4.trans.shared.b16 {%0,%1,%2,%3}, [%4];"
                 : "=r"(r[0]), "=r"(r[1]), "=r"(r[2]), "=r"(r[3]) : "r"(addr));
}
__device__ __forceinline__ void ldsm_x2(uint32_t* r, uint32_t addr) {
    asm volatile("ldmatrix.sync.aligned.m8n8.x2.shared.b16 {%0,%1}, [%2];"
                 : "=r"(r[0]), "=r"(r[1]) : "r"(addr));
}
__device__ __forceinline__ void cp_async16(uint32_t dst, const void* src) {
    asm volatile("cp.async.cg.shared.global [%0], [%1], 16;" :: "r"(dst), "l"(src));
}
__device__ __forceinline__ void cp_async16z(uint32_t dst, const void* src, int sz) {
    asm volatile("cp.async.cg.shared.global [%0], [%1], 16, %2;"
                 :: "r"(dst), "l"(src), "r"(sz));
}
#define CP_COMMIT()  asm volatile("cp.async.commit_group;" ::: "memory")
#define CP_WAIT_1()  asm volatile("cp.async.wait_group 1;" ::: "memory")
#define CP_WAIT_0()  asm volatile("cp.async.wait_group 0;" ::: "memory")

__device__ __forceinline__ uint32_t pack_hl(float v, float w, uint32_t& lo) {
    __nv_bfloat16 h0 = __float2bfloat16(v);
    __nv_bfloat16 h1 = __float2bfloat16(w);
    __nv_bfloat16 l0 = __float2bfloat16(v - __bfloat162float(h0));
    __nv_bfloat16 l1 = __float2bfloat16(w - __bfloat162float(h1));
    lo = (uint32_t)__bfloat16_as_ushort(l0) | ((uint32_t)__bfloat16_as_ushort(l1) << 16);
    return (uint32_t)__bfloat16_as_ushort(h0) | ((uint32_t)__bfloat16_as_ushort(h1) << 16);
}

// ---------------------------------------------------------------------------
// convert x (fp32) -> hi/lo bf16
// ---------------------------------------------------------------------------
__global__ void convert_x_kernel(const float* __restrict__ X,
                                 __nv_bfloat16* __restrict__ Xh,
                                 __nv_bfloat16* __restrict__ Xl) {
    const int i = (blockIdx.x * blockDim.x + threadIdx.x) * 4;
    const float4 v = *(const float4*)(X + i);
    uint32_t h0, h1, l0, l1;
    h0 = pack_hl(v.x, v.y, l0);
    h1 = pack_hl(v.z, v.w, l1);
    *(uint2*)(Xh + i) = make_uint2(h0, h1);
    *(uint2*)(Xl + i) = make_uint2(l0, l1);
}

// ---------------------------------------------------------------------------
// convert + transpose W[768 in, 768 out] -> Wt[out, in] hi/lo bf16
// ---------------------------------------------------------------------------
__global__ void convert_wt_kernel(const float* __restrict__ W,
                                  __nv_bfloat16* __restrict__ Wth,
                                  __nv_bfloat16* __restrict__ Wtl) {
    __shared__ float tile[32][33];
    const int bx = blockIdx.x * 32;
    const int by = blockIdx.y * 32;
    const int tx = threadIdx.x, ty = threadIdx.y;
    for (int r = ty; r < 32; r += 8)
        tile[r][tx] = W[(size_t)(by + r) * DD + bx + tx];
    __syncthreads();
    for (int r = ty; r < 32; r += 8) {
        const float v = tile[tx][r];
        const __nv_bfloat16 h = __float2bfloat16(v);
        const __nv_bfloat16 l = __float2bfloat16(v - __bfloat162float(h));
        const size_t o = (size_t)(bx + r) * DD + by + tx;
        Wth[o] = h;
        Wtl[o] = l;
    }
}

// ---------------------------------------------------------------------------
// bf16x3 GEMM via mma.sync; output always bf16 hi/lo (+bias, optional GELU)
// ---------------------------------------------------------------------------
template<int GELU>
__global__ void __launch_bounds__(256) mma_gemm_kernel(
    const __nv_bfloat16* __restrict__ Ah, const __nv_bfloat16* __restrict__ Al,
    const __nv_bfloat16* __restrict__ Bh, const __nv_bfloat16* __restrict__ Bl,
    const float* __restrict__ bias,
    __nv_bfloat16* __restrict__ Ch, __nv_bfloat16* __restrict__ Cl)
{
    extern __shared__ char sm[];
    const uint32_t smb = s2u(sm);

    const int t    = threadIdx.x;
    const int warp = t >> 5;
    const int lane = t & 31;
    const int wm   = warp >> 2;
    const int wn   = warp & 3;
    const int n0   = blockIdx.x * 128;
    const int m0   = blockIdx.y * 128;

    const __nv_bfloat16* srcs[4] = {Ah, Al, Bh, Bl};
    const int row0g[4] = {m0, m0, n0, n0};
    auto prefetch = [&](int c, int s) {
        const int k0 = c * BK;
        const uint32_t sb = smb + s * STAGE_SM;
        #pragma unroll
        for (int i = 0; i < 8; i++) {
            const int idx  = t + 256 * i;
            const int tile = idx >> 9;
            const int rem  = idx & 511;
            const int row  = rem >> 2;
            const int cc   = rem & 3;
            const uint32_t dst = sb + tile * TILE_SM + (row * PADK + cc * 8) * 2;
            cp_async16(dst, srcs[tile] + (size_t)(row0g[tile] + row) * DD + k0 + cc * 8);
        }
        CP_COMMIT();
    };

    const int arow   = (lane & 15);
    const int acol8  = (lane >> 4) * 8;
    const int q      = lane >> 3;
    const int brl    = lane & 7;
    const int brow   = (q < 2) ? brl : (8 + brl);
    const int bcol8  = (q & 1) * 8;

    const uint32_t aoff = ((wm * 64 + arow) * PADK + acol8) * 2;
    const uint32_t boff = ((wn * 32 + brow) * PADK + bcol8) * 2;

    float acc[4][4][4];
    #pragma unroll
    for (int i = 0; i < 4; i++)
        #pragma unroll
        for (int j = 0; j < 4; j++)
            #pragma unroll
            for (int r = 0; r < 4; r++) acc[i][j][r] = 0.f;

    prefetch(0, 0);

    for (int c = 0; c < NC; ++c) {
        const int s = c & 1;
        if (c + 1 < NC) { prefetch(c + 1, s ^ 1); CP_WAIT_1(); }
        else            { CP_WAIT_0(); }
        __syncthreads();

        const uint32_t sb  = smb + s * STAGE_SM;
        const uint32_t sAh = sb;
        const uint32_t sAl = sb + TILE_SM;
        const uint32_t sBh = sb + 2 * TILE_SM;
        const uint32_t sBl = sb + 3 * TILE_SM;

        #pragma unroll
        for (int k16 = 0; k16 < BK; k16 += 16) {
            uint32_t ah[4][4], al[4][4], bh[4][2], bl[4][2];
            #pragma unroll
            for (int mt = 0; mt < 4; mt++) {
                const uint32_t ao = aoff + mt * (16 * PADK * 2) + k16 * 2;
                ldsm_x4(ah[mt], sAh + ao);
                ldsm_x4(al[mt], sAl + ao);
            }
            #pragma unroll
            for (int ntp = 0; ntp < 2; ntp++) {
                const uint32_t bo = boff + ntp * (16 * PADK * 2) + k16 * 2;
                uint32_t rh[4], rl[4];
                ldsm_x4(rh, sBh + bo);
                ldsm_x4(rl, sBl + bo);
                bh[ntp * 2][0] = rh[0]; bh[ntp * 2][1] = rh[1];
                bh[ntp * 2 + 1][0] = rh[2]; bh[ntp * 2 + 1][1] = rh[3];
                bl[ntp * 2][0] = rl[0]; bl[ntp * 2][1] = rl[1];
                bl[ntp * 2 + 1][0] = rl[2]; bl[ntp * 2 + 1][1] = rl[3];
            }
            #pragma unroll
            for (int mt = 0; mt < 4; mt++)
                #pragma unroll
                for (int nt = 0; nt < 4; nt++) {
                    mma_bf16(acc[mt][nt], ah[mt], bh[nt]);
                    mma_bf16(acc[mt][nt], ah[mt], bl[nt]);
                    mma_bf16(acc[mt][nt], al[mt], bh[nt]);
                }
        }
        __syncthreads();
    }

    const int gid = lane >> 2;
    const int qid = lane & 3;
    float bv[4][2];
    #pragma unroll
    for (int nt = 0; nt < 4; nt++) {
        const int col = n0 + wn * 32 + nt * 8 + qid * 2;
        bv[nt][0] = bias[col];
        bv[nt][1] = bias[col + 1];
    }

    #pragma unroll
    for (int mt = 0; mt < 4; mt++) {
        const int row = m0 + wm * 64 + mt * 16 + gid;
        #pragma unroll
        for (int nt = 0; nt < 4; nt++) {
            const int col = n0 + wn * 32 + nt * 8 + qid * 2;
            #pragma unroll
            for (int half = 0; half < 2; half++) {
                float v0 = acc[mt][nt][half * 2]     + bv[nt][0];
                float v1 = acc[mt][nt][half * 2 + 1] + bv[nt][1];
                if (GELU) { v0 = gelu_exact(v0); v1 = gelu_exact(v1); }
                uint32_t lo;
                const uint32_t hi = pack_hl(v0, v1, lo);
                const size_t off = (size_t)(row + half * 8) * DD + col;
                *(uint32_t*)(Ch + off) = hi;
                *(uint32_t*)(Cl + off) = lo;
            }
        }
    }
}

// ---------------------------------------------------------------------------
// Fused banded attention + LayerNorm via mma.sync bf16x3.
// Block = (batch, 32-query tile). 256 threads, 8 warps (2m x 4n).
// ---------------------------------------------------------------------------
__global__ void __launch_bounds__(256) attn_ln_kernel(
    const __nv_bfloat16* __restrict__ Qh, const __nv_bfloat16* __restrict__ Ql,
    const __nv_bfloat16* __restrict__ Kh, const __nv_bfloat16* __restrict__ Kl,
    const __nv_bfloat16* __restrict__ Vh, const __nv_bfloat16* __restrict__ Vl,
    const float* __restrict__ lnw, const float* __restrict__ lnb,
    float* __restrict__ out)
{
    extern __shared__ char smc[];
    const uint32_t smb = s2u(smc);
    const uint32_t smSh = smb + S_H_OFF;
    const uint32_t smSl = smb + S_L_OFF;
    const uint32_t smA  = smb + A_OFF;
    float* Ysh = (float*)(smc + Y_OFF);

    const int t    = threadIdx.x;
    const int warp = t >> 5;
    const int lane = t & 31;
    const int wm   = warp >> 2;        // 0..1
    const int wn   = warp & 3;         // 0..3
    const int gid  = lane >> 2;
    const int qid  = lane & 3;

    const int bx = blockIdx.x;
    const int b  = bx >> 7;
    const int i0 = (bx & 127) * TQ;    // batch-local first query
    const long base = (long)b * 4096;
    const int jb = i0 - 256;           // window start (batch-local)

    // ---- ldmatrix lane addressing pieces ----
    const int l15   = lane & 15;
    const int hi8   = (lane >> 4) * 8;
    const int q3    = lane >> 3;
    const int brl   = lane & 7;
    const int brow  = (q3 < 2) ? brl : (8 + brl);
    const int bcol8 = (q3 & 1) * 8;

    // =================== phase 1: S = mask(Q @ K^T) ===================
    auto p1_prefetch = [&](int c, int s) {
        const int k0 = c * 32;
        const uint32_t sb = smA + s * P1_STAGE;
        #pragma unroll
        for (int i = 0; i < 10; i++) {
            const int idx = t + 256 * i;
            if (idx < 2304) {
                const int hl = idx >= 1152;
                const int r  = (idx - hl * 1152) >> 2;
                const int cc = idx & 3;
                const uint32_t dst = sb + (hl ? P1_KL : P1_KH) + r * (PADK * 2) + cc * 16;
                const int jl = jb + r;
                const int jlc = jl < 0 ? 0 : jl;
                const __nv_bfloat16* src =
                    (hl ? Kl : Kh) + (size_t)(base + jlc) * DD + k0 + cc * 8;
                cp_async16z(dst, src, jl < 0 ? 0 : 16);
            } else {
                const int idq = idx - 2304;
                const int hl = idq >= 128;
                const int r  = (idq - hl * 128) >> 2;
                const int cc = idq & 3;
                const uint32_t dst = sb + (hl ? P1_QL : P1_QH) + r * (PADK * 2) + cc * 16;
                const __nv_bfloat16* src =
                    (hl ? Ql : Qh) + (size_t)(base + i0 + r) * DD + k0 + cc * 8;
                cp_async16(dst, src);
            }
        }
        CP_COMMIT();
    };

    float acc[9][4];
    #pragma unroll
    for (int n = 0; n < 9; n++)
        #pragma unroll
        for (int r = 0; r < 4; r++) acc[n][r] = 0.f;

    p1_prefetch(0, 0);

    for (int c = 0; c < 24; ++c) {
        const int s = c & 1;
        if (c + 1 < 24) { p1_prefetch(c + 1, s ^ 1); CP_WAIT_1(); }
        else            { CP_WAIT_0(); }
        __syncthreads();

        const uint32_t sb = smA + s * P1_STAGE;
        #pragma unroll
        for (int k16 = 0; k16 < 32; k16 += 16) {
            uint32_t ah[4], al[4];
            const uint32_t ao = ((wm * 16 + l15) * PADK + k16 + hi8) * 2;
            ldsm_x4(ah, sb + P1_QH + ao);
            ldsm_x4(al, sb + P1_QL + ao);

            uint32_t bh[9][2], bl[9][2];
            #pragma unroll
            for (int p = 0; p < 4; p++) {
                const int n0 = wn * 72 + p * 16;
                const uint32_t bo = ((n0 + brow) * PADK + k16 + bcol8) * 2;
                uint32_t r4[4];
                ldsm_x4(r4, sb + P1_KH + bo);
                bh[2*p][0] = r4[0]; bh[2*p][1] = r4[1];
                bh[2*p+1][0] = r4[2]; bh[2*p+1][1] = r4[3];
                ldsm_x4(r4, sb + P1_KL + bo);
                bl[2*p][0] = r4[0]; bl[2*p][1] = r4[1];
                bl[2*p+1][0] = r4[2]; bl[2*p+1][1] = r4[3];
            }
            {
                const int n0 = wn * 72 + 64;
                const uint32_t bo2 = ((n0 + brl) * PADK + k16 + ((lane & 8) ? 8 : 0)) * 2;
                ldsm_x2(bh[8], sb + P1_KH + bo2);
                ldsm_x2(bl[8], sb + P1_KL + bo2);
            }
            #pragma unroll
            for (int nt = 0; nt < 9; nt++) {
                mma_bf16(acc[nt], ah, bh[nt]);
                mma_bf16(acc[nt], ah, bl[nt]);
                mma_bf16(acc[nt], al, bh[nt]);
            }
        }
        __syncthreads();
    }

    // mask + scale + split hi/lo into S smem
    #pragma unroll
    for (int nt = 0; nt < 9; nt++) {
        const int jw0 = wn * 72 + nt * 8 + qid * 2;
        #pragma unroll
        for (int half = 0; half < 2; half++) {
            const int ti = wm * 16 + gid + half * 8;
            float v0 = acc[nt][half * 2];
            float v1 = acc[nt][half * 2 + 1];
            const bool ok0 = (jb + jw0     >= 0) && (jw0     > ti) && (jw0     <= ti + 256);
            const bool ok1 = (jb + jw0 + 1 >= 0) && (jw0 + 1 > ti) && (jw0 + 1 <= ti + 256);
            v0 = ok0 ? v0 * INV_SCALE : 0.f;
            v1 = ok1 ? v1 * INV_SCALE : 0.f;
            uint32_t lo;
            const uint32_t hi = pack_hl(v0, v1, lo);
            const uint32_t so = (ti * SSTR + jw0) * 2;
            *(uint32_t*)(smc + S_H_OFF + so) = hi;
            *(uint32_t*)(smc + S_L_OFF + so) = lo;
        }
    }
    __syncthreads();

    // =================== phase 2: Y = S @ V ===================
    auto p2_prefetch = [&](int iter, int s) {
        const int dc = (iter / 9) * 256;
        const int js = (iter % 9) * 32;
        const uint32_t sb = smA + s * P2_STAGE;
        #pragma unroll
        for (int i = 0; i < 8; i++) {
            const int idx = t + 256 * i;
            const int hl  = idx >= 1024;
            const int idv = idx - hl * 1024;
            const int r   = idv >> 5;
            const int cc  = idv & 31;
            const uint32_t dst = sb + (hl ? P2_VL : P2_VH) + r * (VSTR * 2) + cc * 16;
            const int jl  = jb + js + r;
            const int jlc = jl < 0 ? 0 : jl;
            const __nv_bfloat16* src =
                (hl ? Vl : Vh) + (size_t)(base + jlc) * DD + dc + cc * 8;
            cp_async16z(dst, src, jl < 0 ? 0 : 16);
        }
        CP_COMMIT();
    };

    float acc2[8][4];
    #pragma unroll
    for (int n = 0; n < 8; n++)
        #pragma unroll
        for (int r = 0; r < 4; r++) acc2[n][r] = 0.f;

    p2_prefetch(0, 0);

    for (int iter = 0; iter < 27; ++iter) {
        const int s = iter & 1;
        if (iter + 1 < 27) { p2_prefetch(iter + 1, s ^ 1); CP_WAIT_1(); }
        else               { CP_WAIT_0(); }
        __syncthreads();

        const int js = (iter % 9) * 32;
        const uint32_t sb = smA + s * P2_STAGE;
        #pragma unroll
        for (int k16 = 0; k16 < 32; k16 += 16) {
            uint32_t ah[4], al[4];
            const uint32_t ao = ((wm * 16 + l15) * SSTR + js + k16 + hi8) * 2;
            ldsm_x4(ah, smSh + ao);
            ldsm_x4(al, smSl + ao);

            uint32_t bh[8][2], bl[8][2];
            #pragma unroll
            for (int p = 0; p < 4; p++) {
                const int n0 = wn * 64 + p * 16;
                const uint32_t bo = ((k16 + l15) * VSTR + n0 + hi8) * 2;
                uint32_t r4[4];
                ldsm_x4_t(r4, sb + P2_VH + bo);
                bh[2*p][0] = r4[0]; bh[2*p][1] = r4[1];
                bh[2*p+1][0] = r4[2]; bh[2*p+1][1] = r4[3];
                ldsm_x4_t(r4, sb + P2_VL + bo);
                bl[2*p][0] = r4[0]; bl[2*p][1] = r4[1];
                bl[2*p+1][0] = r4[2]; bl[2*p+1][1] = r4[3];
            }
            #pragma unroll
            for (int nt = 0; nt < 8; nt++) {
                mma_bf16(acc2[nt], ah, bh[nt]);
                mma_bf16(acc2[nt], ah, bl[nt]);
                mma_bf16(acc2[nt], al, bh[nt]);
            }
        }

        if ((iter % 9) == 8) {
            const int dc = (iter / 9) * 256;
            #pragma unroll
            for (int nt = 0; nt < 8; nt++) {
                const int col = dc + wn * 64 + nt * 8 + qid * 2;
                #pragma unroll
                for (int half = 0; half < 2; half++) {
                    const int row = wm * 16 + gid + half * 8;
                    *(float2*)&Ysh[row * DD + col] =
                        make_float2(acc2[nt][half * 2], acc2[nt][half * 2 + 1]);
                }
            }
            #pragma unroll
            for (int n = 0; n < 8; n++)
                #pragma unroll
                for (int r = 0; r < 4; r++) acc2[n][r] = 0.f;
        }
        __syncthreads();
    }

    // =================== phase 3: LayerNorm ===================
    {
        #pragma unroll
        for (int rr = 0; rr < 4; rr++) {
            const int row = warp * 4 + rr;
            float s = 0.f, ss = 0.f;
            #pragma unroll
            for (int c0 = 0; c0 < DD; c0 += 32) {
                const float y = Ysh[row * DD + c0 + lane];
                s += y; ss += y * y;
            }
            #pragma unroll
            for (int o = 16; o > 0; o >>= 1) {
                s  += __shfl_xor_sync(0xffffffffu, s,  o);
                ss += __shfl_xor_sync(0xffffffffu, ss, o);
            }
            const float mu   = s * (1.f / 768.f);
            const float var  = ss * (1.f / 768.f) - mu * mu;
            const float rstd = rsqrtf(var + 1e-5f);
            #pragma unroll
            for (int c0 = 0; c0 < DD; c0 += 32) {
                const int c = c0 + lane;
                const float y = Ysh[row * DD + c];
                out[(base + i0 + row) * DD + c] = (y - mu) * rstd * lnw[c] + lnb[c];
            }
        }
    }
}

// ---------------------------------------------------------------------------
extern "C" void kernel_launch(void* const* d_in, const int* in_sizes, int n_in,
                              void* d_out, int out_size)
{
    const float* x   = (const float*)d_in[0];
    const float* qw1 = (const float*)d_in[1];
    const float* qb1 = (const float*)d_in[2];
    const float* qw2 = (const float*)d_in[3];
    const float* qb2 = (const float*)d_in[4];
    const float* kw1 = (const float*)d_in[5];
    const float* kb1 = (const float*)d_in[6];
    const float* kw2 = (const float*)d_in[7];
    const float* kb2 = (const float*)d_in[8];
    const float* vw1 = (const float*)d_in[9];
    const float* vb1 = (const float*)d_in[10];
    const float* vw2 = (const float*)d_in[11];
    const float* vb2 = (const float*)d_in[12];
    const float* lnw = (const float*)d_in[13];
    const float* lnb = (const float*)d_in[14];
    float* out = (float*)d_out;

    __nv_bfloat16 *Xh, *Xl, *Hh, *Hl, *Wth, *Wtl, *Qh, *Ql, *Kh, *Kl, *Vh, *Vl;
    cudaGetSymbolAddress((void**)&Xh, g_Xh);
    cudaGetSymbolAddress((void**)&Xl, g_Xl);
    cudaGetSymbolAddress((void**)&Hh, g_Hh);
    cudaGetSymbolAddress((void**)&Hl, g_Hl);
    cudaGetSymbolAddress((void**)&Wth, g_Wth);
    cudaGetSymbolAddress((void**)&Wtl, g_Wtl);
    cudaGetSymbolAddress((void**)&Qh, g_Qh);
    cudaGetSymbolAddress((void**)&Ql, g_Ql);
    cudaGetSymbolAddress((void**)&Kh, g_Kh);
    cudaGetSymbolAddress((void**)&Kl, g_Kl);
    cudaGetSymbolAddress((void**)&Vh, g_Vh);
    cudaGetSymbolAddress((void**)&Vl, g_Vl);

    const int gemm_smem = 2 * STAGE_SM;   // 81920
    cudaFuncSetAttribute(mma_gemm_kernel<0>,
                         cudaFuncAttributeMaxDynamicSharedMemorySize, gemm_smem);
    cudaFuncSetAttribute(mma_gemm_kernel<1>,
                         cudaFuncAttributeMaxDynamicSharedMemorySize, gemm_smem);
    cudaFuncSetAttribute(attn_ln_kernel,
                         cudaFuncAttributeMaxDynamicSharedMemorySize, ATTN_SMEM);

    convert_x_kernel<<<(MT * DD) / (256 * 4), 256>>>(x, Xh, Xl);

    const dim3 gw(24, 24);
    const dim3 bw(32, 8);
    const dim3 gg(DD / 128, MT / 128);

    const float* W1[3] = {qw1, kw1, vw1};
    const float* B1[3] = {qb1, kb1, vb1};
    const float* W2[3] = {qw2, kw2, vw2};
    const float* B2[3] = {qb2, kb2, vb2};
    __nv_bfloat16* OH[3] = {Qh, Kh, Vh};
    __nv_bfloat16* OL[3] = {Ql, Kl, Vl};

    for (int m = 0; m < 3; m++) {
        convert_wt_kernel<<<gw, bw>>>(W1[m], Wth, Wtl);
        mma_gemm_kernel<1><<<gg, 256, gemm_smem>>>(Xh, Xl, Wth, Wtl, B1[m], Hh, Hl);
        convert_wt_kernel<<<gw, bw>>>(W2[m], Wth, Wtl);
        mma_gemm_kernel<0><<<gg, 256, gemm_smem>>>(Hh, Hl, Wth, Wtl, B2[m], OH[m], OL[m]);
    }

    attn_ln_kernel<<<MT / TQ, 256, ATTN_SMEM>>>(Qh, Ql, Kh, Kl, Vh, Vl, lnw, lnb, out);
}

// round 6
// speedup vs baseline: 1.2615x; 1.2615x over previous
#include <cuda_runtime.h>
#include <cuda_bf16.h>
#include <math.h>
#include <stdint.h>

#define MT 16384
#define DD 768
#define NCH 12                       // K chunks of 64
#define A_PLANE (MT * 128)           // bytes per chunk plane (M=16384)
#define W_PLANE (DD * 128)           // bytes per chunk plane (M=768)
#define SZ_X ((size_t)MT * DD * 2)   // bytes of one [MT][768] bf16 buffer
#define SZ_W ((size_t)DD * DD * 2)

// GEMM smem stage: Ah 32K | Al 32K | Bh 16K | Bl 16K
#define STG_AL 32768
#define STG_BH 65536
#define STG_BL 81920
#define STAGE  98304
#define GEMM_SMEM (2 * STAGE)

// ---- attention (unchanged from round 4) ----
#define TQ 32
#define JW 288
#define SSTR 296
#define VSTR 264
#define S_H_OFF 0
#define S_L_OFF 18944
#define A_OFF   37888
#define P1_STAGE 51200
#define P1_KH 0
#define P1_KL 23040
#define P1_QH 46080
#define P1_QL 48640
#define P2_STAGE 33792
#define P2_VH 0
#define P2_VL 16896
#define Y_OFF  105472
#define ATTN_SMEM 203776
#define PADK 40

#define INV_SCALE 0.0022552744890219756f

// ---------------------------------------------------------------------------
// scratch (device globals)
// ---------------------------------------------------------------------------
__device__ __align__(128) uint8_t g_Xh[SZ_X];
__device__ __align__(128) uint8_t g_Xl[SZ_X];
__device__ __align__(128) uint8_t g_Hh[3 * SZ_X];
__device__ __align__(128) uint8_t g_Hl[3 * SZ_X];
__device__ __align__(128) uint8_t g_W1h[3 * SZ_W];
__device__ __align__(128) uint8_t g_W1l[3 * SZ_W];
__device__ __align__(128) uint8_t g_W2h[3 * SZ_W];
__device__ __align__(128) uint8_t g_W2l[3 * SZ_W];
__device__ __nv_bfloat16 g_QKVh[3ull * MT * DD];
__device__ __nv_bfloat16 g_QKVl[3ull * MT * DD];

__device__ __forceinline__ float gelu_exact(float x) {
    return 0.5f * x * (1.0f + erff(x * 0.70710678118654752f));
}
__device__ __forceinline__ uint32_t s2u(const void* p) {
    uint32_t a;
    asm("{ .reg .u64 t; cvta.to.shared.u64 t, %1; cvt.u32.u64 %0, t; }"
        : "=r"(a) : "l"(p));
    return a;
}
// swizzled tiled byte offset of element (row, k)
__device__ __forceinline__ size_t toff(int row, int k, size_t plane) {
    const int u = ((k >> 3) & 7) ^ (row & 7);
    return (size_t)(k >> 6) * plane + (size_t)row * 128 + (size_t)(u << 4) + (size_t)(k & 7) * 2;
}

// ---- tensor-core + async primitives (all base features) ----
__device__ __forceinline__ void mma_bf16(float* c, const uint32_t* a, const uint32_t* b) {
    asm volatile(
        "mma.sync.aligned.m16n8k16.row.col.f32.bf16.bf16.f32 "
        "{%0,%1,%2,%3}, {%4,%5,%6,%7}, {%8,%9}, {%0,%1,%2,%3};"
        : "+f"(c[0]), "+f"(c[1]), "+f"(c[2]), "+f"(c[3])
        : "r"(a[0]), "r"(a[1]), "r"(a[2]), "r"(a[3]), "r"(b[0]), "r"(b[1]));
}
__device__ __forceinline__ void ldsm_x4(uint32_t* r, uint32_t addr) {
    asm volatile("ldmatrix.sync.aligned.m8n8.x4.shared.b16 {%0,%1,%2,%3}, [%4];"
                 : "=r"(r[0]), "=r"(r[1]), "=r"(r[2]), "=r"(r[3]) : "r"(addr));
}
__device__ __forceinline__ void ldsm_x4_t(uint32_t* r, uint32_t addr) {
    asm volatile("ldmatrix.sync.aligned.m8n8.x4.trans.shared.b16 {%0,%1,%2,%3}, [%4];"
                 : "=r"(r[0]), "=r"(r[1]), "=r"(r[2]), "=r"(r[3]) : "r"(addr));
}
__device__ __forceinline__ void ldsm_x2(uint32_t* r, uint32_t addr) {
    asm volatile("ldmatrix.sync.aligned.m8n8.x2.shared.b16 {%0,%1}, [%2];"
                 : "=r"(r[0]), "=r"(r[1]) : "r"(addr));
}
__device__ __forceinline__ void cp_async16(uint32_t dst, const void* src) {
    asm volatile("cp.async.cg.shared.global [%0], [%1], 16;" :: "r"(dst), "l"(src));
}
__device__ __forceinline__ void cp_async16z(uint32_t dst, const void* src, int sz) {
    asm volatile("cp.async.cg.shared.global [%0], [%1], 16, %2;"
                 :: "r"(dst), "l"(src), "r"(sz));
}
#define CP_COMMIT()  asm volatile("cp.async.commit_group;" ::: "memory")
#define CP_WAIT_1()  asm volatile("cp.async.wait_group 1;" ::: "memory")
#define CP_WAIT_0()  asm volatile("cp.async.wait_group 0;" ::: "memory")

#define MB_INIT(addr, cnt) \
    asm volatile("mbarrier.init.shared.b64 [%0], %1;" :: "r"(addr), "r"(cnt) : "memory")
#define MB_EXPECT(addr, tx) \
    asm volatile("mbarrier.arrive.expect_tx.shared.b64 _, [%0], %1;" :: "r"(addr), "r"(tx) : "memory")
#define BULK_G2S(dst, src, sz, mb) \
    asm volatile("cp.async.bulk.shared::cluster.global.mbarrier::complete_tx::bytes [%0], [%1], %2, [%3];" \
                 :: "r"(dst), "l"(src), "r"(sz), "r"(mb) : "memory")
#define MB_WAIT(addr, par) do {                                                \
    uint32_t _m = (addr), _p = (par), _d;                                      \
    asm volatile("{\n\t.reg .pred p;\n\t"                                      \
        "mbarrier.try_wait.parity.acquire.cta.shared::cta.b64 p, [%1], %2;\n\t"\
        "selp.b32 %0, 1, 0, p;\n\t}"                                           \
        : "=r"(_d) : "r"(_m), "r"(_p) : "memory");                             \
    if (!_d) {                                                                 \
        asm volatile("{\n\t.reg .pred P1;\n\t"                                 \
            "WL_%=:\n\t"                                                       \
            "mbarrier.try_wait.parity.acquire.cta.shared::cta.b64 P1, [%0], %1, 0x989680;\n\t" \
            "@P1 bra.uni WD_%=;\n\t"                                           \
            "bra.uni WL_%=;\n\t"                                               \
            "WD_%=:\n\t}"                                                      \
            :: "r"(_m), "r"(_p) : "memory");                                   \
    }                                                                          \
} while (0)

__device__ __forceinline__ uint32_t pack_hl(float v, float w, uint32_t& lo) {
    __nv_bfloat16 h0 = __float2bfloat16(v);
    __nv_bfloat16 h1 = __float2bfloat16(w);
    __nv_bfloat16 l0 = __float2bfloat16(v - __bfloat162float(h0));
    __nv_bfloat16 l1 = __float2bfloat16(w - __bfloat162float(h1));
    lo = (uint32_t)__bfloat16_as_ushort(l0) | ((uint32_t)__bfloat16_as_ushort(l1) << 16);
    return (uint32_t)__bfloat16_as_ushort(h0) | ((uint32_t)__bfloat16_as_ushort(h1) << 16);
}

// ---------------------------------------------------------------------------
// convert x -> tiled hi/lo bf16 (8 elems = 1 16B unit per thread)
// ---------------------------------------------------------------------------
__global__ void convert_x_kernel(const float* __restrict__ X,
                                 uint8_t* __restrict__ Xh,
                                 uint8_t* __restrict__ Xl) {
    const long gi = (long)(blockIdx.x * blockDim.x + threadIdx.x) * 8;
    const int row = (int)(gi / DD);
    const int k   = (int)(gi % DD);
    const float4 v0 = *(const float4*)(X + gi);
    const float4 v1 = *(const float4*)(X + gi + 4);
    uint32_t h[4], l[4];
    h[0] = pack_hl(v0.x, v0.y, l[0]);
    h[1] = pack_hl(v0.z, v0.w, l[1]);
    h[2] = pack_hl(v1.x, v1.y, l[2]);
    h[3] = pack_hl(v1.z, v1.w, l[3]);
    const size_t o = toff(row, k, A_PLANE);
    *(uint4*)(Xh + o) = make_uint4(h[0], h[1], h[2], h[3]);
    *(uint4*)(Xl + o) = make_uint4(l[0], l[1], l[2], l[3]);
}

// ---------------------------------------------------------------------------
// convert + transpose W[in,out] -> tiled Wt[out,in] hi/lo
// ---------------------------------------------------------------------------
__global__ void convert_wt_kernel(const float* __restrict__ W,
                                  uint8_t* __restrict__ Wth,
                                  uint8_t* __restrict__ Wtl) {
    __shared__ float tile[32][33];
    const int bx = blockIdx.x * 32;
    const int by = blockIdx.y * 32;
    const int tx = threadIdx.x, ty = threadIdx.y;
    for (int r = ty; r < 32; r += 8)
        tile[r][tx] = W[(size_t)(by + r) * DD + bx + tx];
    __syncthreads();
    for (int r = ty; r < 32; r += 8) {
        const float v = tile[tx][r];               // = W[by+tx][bx+r] = Wt[bx+r][by+tx]
        const __nv_bfloat16 h = __float2bfloat16(v);
        const __nv_bfloat16 l = __float2bfloat16(v - __bfloat162float(h));
        const size_t o = toff(bx + r, by + tx, W_PLANE);
        *(__nv_bfloat16*)(Wth + o) = h;
        *(__nv_bfloat16*)(Wtl + o) = l;
    }
}

// ---------------------------------------------------------------------------
// bf16x3 GEMM, cp.async.bulk pipeline.  CTA tile 256x128, 512 threads.
// LAYER 1: gelu(acc+bias) -> tiled H (zstride SZ_X), A = X (zstride 0)
// LAYER 2: acc+bias       -> row-major QKV,          A = H (zstride SZ_X)
// ---------------------------------------------------------------------------
template<int LAYER>
__global__ void __launch_bounds__(512) mma_gemm_kernel(
    const uint8_t* __restrict__ Abh, const uint8_t* __restrict__ Abl,
    const uint8_t* __restrict__ Bbh, const uint8_t* __restrict__ Bbl,
    const float* __restrict__ bias0, const float* __restrict__ bias1,
    const float* __restrict__ bias2,
    uint8_t* __restrict__ Ch, uint8_t* __restrict__ Cl)
{
    extern __shared__ char sm[];
    __shared__ uint64_t s_mbar[2];
    const uint32_t smb = s2u(sm);
    const uint32_t mb0 = s2u(&s_mbar[0]);

    const int t    = threadIdx.x;
    const int warp = t >> 5;
    const int lane = t & 31;
    const int wm   = warp & 7;         // 0..7 (32-row slabs)
    const int wn   = warp >> 3;        // 0..1 (64-col slabs)
    const int n0   = blockIdx.x * 128;
    const int m0   = blockIdx.y * 256;
    const int z    = blockIdx.z;

    const uint8_t* Ah = Abh + (LAYER == 2 ? (size_t)z * SZ_X : 0);
    const uint8_t* Al = Abl + (LAYER == 2 ? (size_t)z * SZ_X : 0);
    const uint8_t* Bh = Bbh + (size_t)z * SZ_W;
    const uint8_t* Bl = Bbl + (size_t)z * SZ_W;
    const float* bias = (z == 0) ? bias0 : (z == 1) ? bias1 : bias2;

    if (t == 0) { MB_INIT(mb0, 1); MB_INIT(mb0 + 8, 1); }
    __syncthreads();

    auto load_chunk = [&](int c, int s) {
        if (t == 0) {
            const uint32_t sb = smb + s * STAGE;
            const uint32_t mb = mb0 + s * 8;
            MB_EXPECT(mb, STAGE);
            BULK_G2S(sb,          Ah + (size_t)c * A_PLANE + (size_t)m0 * 128, 32768, mb);
            BULK_G2S(sb + STG_AL, Al + (size_t)c * A_PLANE + (size_t)m0 * 128, 32768, mb);
            BULK_G2S(sb + STG_BH, Bh + (size_t)c * W_PLANE + (size_t)n0 * 128, 16384, mb);
            BULK_G2S(sb + STG_BL, Bl + (size_t)c * W_PLANE + (size_t)n0 * 128, 16384, mb);
        }
    };

    // ldmatrix lane pieces
    const int l15   = lane & 15;
    const int uA    = lane >> 4;              // +unit for hi half
    const int q3    = lane >> 3;
    const int brl   = lane & 7;
    const int brow  = (q3 < 2) ? brl : (8 + brl);
    const int uB    = q3 & 1;

    float acc[2][8][4];
    #pragma unroll
    for (int i = 0; i < 2; i++)
        #pragma unroll
        for (int j = 0; j < 8; j++)
            #pragma unroll
            for (int r = 0; r < 4; r++) acc[i][j][r] = 0.f;

    load_chunk(0, 0);
    int ph[2] = {0, 0};

    for (int c = 0; c < NCH; ++c) {
        const int s = c & 1;
        if (c + 1 < NCH) load_chunk(c + 1, s ^ 1);
        MB_WAIT(mb0 + s * 8, ph[s]);
        ph[s] ^= 1;

        const uint32_t sb  = smb + s * STAGE;
        #pragma unroll
        for (int k16 = 0; k16 < 64; k16 += 16) {
            uint32_t ah[2][4], al[2][4];
            #pragma unroll
            for (int mt = 0; mt < 2; mt++) {
                const int row = wm * 32 + mt * 16 + l15;
                const int u   = ((k16 >> 3) + uA) ^ (row & 7);
                const uint32_t ao = (uint32_t)(row * 128 + (u << 4));
                ldsm_x4(ah[mt], sb + ao);
                ldsm_x4(al[mt], sb + STG_AL + ao);
            }
            #pragma unroll
            for (int p = 0; p < 4; p++) {
                const int row = wn * 64 + p * 16 + brow;
                const int u   = ((k16 >> 3) + uB) ^ (row & 7);
                const uint32_t bo = (uint32_t)(row * 128 + (u << 4));
                uint32_t rh[4], rl[4];
                ldsm_x4(rh, sb + STG_BH + bo);
                ldsm_x4(rl, sb + STG_BL + bo);
                #pragma unroll
                for (int h = 0; h < 2; h++) {
                    const int nt = 2 * p + h;
                    #pragma unroll
                    for (int mt = 0; mt < 2; mt++) {
                        mma_bf16(acc[mt][nt], ah[mt], rh + 2 * h);
                        mma_bf16(acc[mt][nt], ah[mt], rl + 2 * h);
                        mma_bf16(acc[mt][nt], al[mt], rh + 2 * h);
                    }
                }
            }
        }
        __syncthreads();   // all warps done with stage s before reload at c+2
    }

    // ---- epilogue ----
    const int gid = lane >> 2;
    const int qid = lane & 3;
    #pragma unroll
    for (int mt = 0; mt < 2; mt++) {
        #pragma unroll
        for (int nt = 0; nt < 8; nt++) {
            const int col = n0 + wn * 64 + nt * 8 + qid * 2;
            const float b0 = bias[col], b1 = bias[col + 1];
            #pragma unroll
            for (int half = 0; half < 2; half++) {
                const int row = m0 + wm * 32 + mt * 16 + gid + half * 8;
                float v0 = acc[mt][nt][half * 2]     + b0;
                float v1 = acc[mt][nt][half * 2 + 1] + b1;
                if (LAYER == 1) { v0 = gelu_exact(v0); v1 = gelu_exact(v1); }
                uint32_t lo;
                const uint32_t hi = pack_hl(v0, v1, lo);
                if (LAYER == 1) {
                    const size_t o = (size_t)z * SZ_X + toff(row, col, A_PLANE);
                    *(uint32_t*)(Ch + o) = hi;
                    *(uint32_t*)(Cl + o) = lo;
                } else {
                    const size_t o = ((size_t)z * MT * DD + (size_t)row * DD + col) * 2;
                    *(uint32_t*)(Ch + o) = hi;
                    *(uint32_t*)(Cl + o) = lo;
                }
            }
        }
    }
}

// ---------------------------------------------------------------------------
// Fused banded attention + LayerNorm (verbatim from round 4 — proven).
// ---------------------------------------------------------------------------
__global__ void __launch_bounds__(256) attn_ln_kernel(
    const __nv_bfloat16* __restrict__ Qh, const __nv_bfloat16* __restrict__ Ql,
    const __nv_bfloat16* __restrict__ Kh, const __nv_bfloat16* __restrict__ Kl,
    const __nv_bfloat16* __restrict__ Vh, const __nv_bfloat16* __restrict__ Vl,
    const float* __restrict__ lnw, const float* __restrict__ lnb,
    float* __restrict__ out)
{
    extern __shared__ char smc[];
    const uint32_t smb = s2u(smc);
    const uint32_t smSh = smb + S_H_OFF;
    const uint32_t smSl = smb + S_L_OFF;
    const uint32_t smA  = smb + A_OFF;
    float* Ysh = (float*)(smc + Y_OFF);

    const int t    = threadIdx.x;
    const int warp = t >> 5;
    const int lane = t & 31;
    const int wm   = warp >> 2;
    const int wn   = warp & 3;
    const int gid  = lane >> 2;
    const int qid  = lane & 3;

    const int bx = blockIdx.x;
    const int b  = bx >> 7;
    const int i0 = (bx & 127) * TQ;
    const long base = (long)b * 4096;
    const int jb = i0 - 256;

    const int l15   = lane & 15;
    const int hi8   = (lane >> 4) * 8;
    const int q3    = lane >> 3;
    const int brl   = lane & 7;
    const int brow  = (q3 < 2) ? brl : (8 + brl);
    const int bcol8 = (q3 & 1) * 8;

    auto p1_prefetch = [&](int c, int s) {
        const int k0 = c * 32;
        const uint32_t sb = smA + s * P1_STAGE;
        #pragma unroll
        for (int i = 0; i < 10; i++) {
            const int idx = t + 256 * i;
            if (idx < 2304) {
                const int hl = idx >= 1152;
                const int r  = (idx - hl * 1152) >> 2;
                const int cc = idx & 3;
                const uint32_t dst = sb + (hl ? P1_KL : P1_KH) + r * (PADK * 2) + cc * 16;
                const int jl = jb + r;
                const int jlc = jl < 0 ? 0 : jl;
                const __nv_bfloat16* src =
                    (hl ? Kl : Kh) + (size_t)(base + jlc) * DD + k0 + cc * 8;
                cp_async16z(dst, src, jl < 0 ? 0 : 16);
            } else {
                const int idq = idx - 2304;
                const int hl = idq >= 128;
                const int r  = (idq - hl * 128) >> 2;
                const int cc = idq & 3;
                const uint32_t dst = sb + (hl ? P1_QL : P1_QH) + r * (PADK * 2) + cc * 16;
                const __nv_bfloat16* src =
                    (hl ? Ql : Qh) + (size_t)(base + i0 + r) * DD + k0 + cc * 8;
                cp_async16(dst, src);
            }
        }
        CP_COMMIT();
    };

    float acc[9][4];
    #pragma unroll
    for (int n = 0; n < 9; n++)
        #pragma unroll
        for (int r = 0; r < 4; r++) acc[n][r] = 0.f;

    p1_prefetch(0, 0);

    for (int c = 0; c < 24; ++c) {
        const int s = c & 1;
        if (c + 1 < 24) { p1_prefetch(c + 1, s ^ 1); CP_WAIT_1(); }
        else            { CP_WAIT_0(); }
        __syncthreads();

        const uint32_t sb = smA + s * P1_STAGE;
        #pragma unroll
        for (int k16 = 0; k16 < 32; k16 += 16) {
            uint32_t ah[4], al[4];
            const uint32_t ao = ((wm * 16 + l15) * PADK + k16 + hi8) * 2;
            ldsm_x4(ah, sb + P1_QH + ao);
            ldsm_x4(al, sb + P1_QL + ao);

            uint32_t bh[9][2], bl[9][2];
            #pragma unroll
            for (int p = 0; p < 4; p++) {
                const int nn0 = wn * 72 + p * 16;
                const uint32_t bo = ((nn0 + brow) * PADK + k16 + bcol8) * 2;
                uint32_t r4[4];
                ldsm_x4(r4, sb + P1_KH + bo);
                bh[2*p][0] = r4[0]; bh[2*p][1] = r4[1];
                bh[2*p+1][0] = r4[2]; bh[2*p+1][1] = r4[3];
                ldsm_x4(r4, sb + P1_KL + bo);
                bl[2*p][0] = r4[0]; bl[2*p][1] = r4[1];
                bl[2*p+1][0] = r4[2]; bl[2*p+1][1] = r4[3];
            }
            {
                const int nn0 = wn * 72 + 64;
                const uint32_t bo2 = ((nn0 + brl) * PADK + k16 + ((lane & 8) ? 8 : 0)) * 2;
                ldsm_x2(bh[8], sb + P1_KH + bo2);
                ldsm_x2(bl[8], sb + P1_KL + bo2);
            }
            #pragma unroll
            for (int nt = 0; nt < 9; nt++) {
                mma_bf16(acc[nt], ah, bh[nt]);
                mma_bf16(acc[nt], ah, bl[nt]);
                mma_bf16(acc[nt], al, bh[nt]);
            }
        }
        __syncthreads();
    }

    #pragma unroll
    for (int nt = 0; nt < 9; nt++) {
        const int jw0 = wn * 72 + nt * 8 + qid * 2;
        #pragma unroll
        for (int half = 0; half < 2; half++) {
            const int ti = wm * 16 + gid + half * 8;
            float v0 = acc[nt][half * 2];
            float v1 = acc[nt][half * 2 + 1];
            const bool ok0 = (jb + jw0     >= 0) && (jw0     > ti) && (jw0     <= ti + 256);
            const bool ok1 = (jb + jw0 + 1 >= 0) && (jw0 + 1 > ti) && (jw0 + 1 <= ti + 256);
            v0 = ok0 ? v0 * INV_SCALE : 0.f;
            v1 = ok1 ? v1 * INV_SCALE : 0.f;
            uint32_t lo;
            const uint32_t hi = pack_hl(v0, v1, lo);
            const uint32_t so = (ti * SSTR + jw0) * 2;
            *(uint32_t*)(smc + S_H_OFF + so) = hi;
            *(uint32_t*)(smc + S_L_OFF + so) = lo;
        }
    }
    __syncthreads();

    auto p2_prefetch = [&](int iter, int s) {
        const int dc = (iter / 9) * 256;
        const int js = (iter % 9) * 32;
        const uint32_t sb = smA + s * P2_STAGE;
        #pragma unroll
        for (int i = 0; i < 8; i++) {
            const int idx = t + 256 * i;
            const int hl  = idx >= 1024;
            const int idv = idx - hl * 1024;
            const int r   = idv >> 5;
            const int cc  = idv & 31;
            const uint32_t dst = sb + (hl ? P2_VL : P2_VH) + r * (VSTR * 2) + cc * 16;
            const int jl  = jb + js + r;
            const int jlc = jl < 0 ? 0 : jl;
            const __nv_bfloat16* src =
                (hl ? Vl : Vh) + (size_t)(base + jlc) * DD + dc + cc * 8;
            cp_async16z(dst, src, jl < 0 ? 0 : 16);
        }
        CP_COMMIT();
    };

    float acc2[8][4];
    #pragma unroll
    for (int n = 0; n < 8; n++)
        #pragma unroll
        for (int r = 0; r < 4; r++) acc2[n][r] = 0.f;

    p2_prefetch(0, 0);

    for (int iter = 0; iter < 27; ++iter) {
        const int s = iter & 1;
        if (iter + 1 < 27) { p2_prefetch(iter + 1, s ^ 1); CP_WAIT_1(); }
        else               { CP_WAIT_0(); }
        __syncthreads();

        const int js = (iter % 9) * 32;
        const uint32_t sb = smA + s * P2_STAGE;
        #pragma unroll
        for (int k16 = 0; k16 < 32; k16 += 16) {
            uint32_t ah[4], al[4];
            const uint32_t ao = ((wm * 16 + l15) * SSTR + js + k16 + hi8) * 2;
            ldsm_x4(ah, smSh + ao);
            ldsm_x4(al, smSl + ao);

            uint32_t bh[8][2], bl[8][2];
            #pragma unroll
            for (int p = 0; p < 4; p++) {
                const int nn0 = wn * 64 + p * 16;
                const uint32_t bo = ((k16 + l15) * VSTR + nn0 + hi8) * 2;
                uint32_t r4[4];
                ldsm_x4_t(r4, sb + P2_VH + bo);
                bh[2*p][0] = r4[0]; bh[2*p][1] = r4[1];
                bh[2*p+1][0] = r4[2]; bh[2*p+1][1] = r4[3];
                ldsm_x4_t(r4, sb + P2_VL + bo);
                bl[2*p][0] = r4[0]; bl[2*p][1] = r4[1];
                bl[2*p+1][0] = r4[2]; bl[2*p+1][1] = r4[3];
            }
            #pragma unroll
            for (int nt = 0; nt < 8; nt++) {
                mma_bf16(acc2[nt], ah, bh[nt]);
                mma_bf16(acc2[nt], ah, bl[nt]);
                mma_bf16(acc2[nt], al, bh[nt]);
            }
        }

        if ((iter % 9) == 8) {
            const int dc = (iter / 9) * 256;
            #pragma unroll
            for (int nt = 0; nt < 8; nt++) {
                const int col = dc + wn * 64 + nt * 8 + qid * 2;
                #pragma unroll
                for (int half = 0; half < 2; half++) {
                    const int row = wm * 16 + gid + half * 8;
                    *(float2*)&Ysh[row * DD + col] =
                        make_float2(acc2[nt][half * 2], acc2[nt][half * 2 + 1]);
                }
            }
            #pragma unroll
            for (int n = 0; n < 8; n++)
                #pragma unroll
                for (int r = 0; r < 4; r++) acc2[n][r] = 0.f;
        }
        __syncthreads();
    }

    {
        #pragma unroll
        for (int rr = 0; rr < 4; rr++) {
            const int row = warp * 4 + rr;
            float s = 0.f, ss = 0.f;
            #pragma unroll
            for (int c0 = 0; c0 < DD; c0 += 32) {
                const float y = Ysh[row * DD + c0 + lane];
                s += y; ss += y * y;
            }
            #pragma unroll
            for (int o = 16; o > 0; o >>= 1) {
                s  += __shfl_xor_sync(0xffffffffu, s,  o);
                ss += __shfl_xor_sync(0xffffffffu, ss, o);
            }
            const float mu   = s * (1.f / 768.f);
            const float var  = ss * (1.f / 768.f) - mu * mu;
            const float rstd = rsqrtf(var + 1e-5f);
            #pragma unroll
            for (int c0 = 0; c0 < DD; c0 += 32) {
                const int c = c0 + lane;
                const float y = Ysh[row * DD + c];
                out[(base + i0 + row) * DD + c] = (y - mu) * rstd * lnw[c] + lnb[c];
            }
        }
    }
}

// ---------------------------------------------------------------------------
extern "C" void kernel_launch(void* const* d_in, const int* in_sizes, int n_in,
                              void* d_out, int out_size)
{
    const float* x   = (const float*)d_in[0];
    const float* qw1 = (const float*)d_in[1];
    const float* qb1 = (const float*)d_in[2];
    const float* qw2 = (const float*)d_in[3];
    const float* qb2 = (const float*)d_in[4];
    const float* kw1 = (const float*)d_in[5];
    const float* kb1 = (const float*)d_in[6];
    const float* kw2 = (const float*)d_in[7];
    const float* kb2 = (const float*)d_in[8];
    const float* vw1 = (const float*)d_in[9];
    const float* vb1 = (const float*)d_in[10];
    const float* vw2 = (const float*)d_in[11];
    const float* vb2 = (const float*)d_in[12];
    const float* lnw = (const float*)d_in[13];
    const float* lnb = (const float*)d_in[14];
    float* out = (float*)d_out;

    uint8_t *Xh, *Xl, *Hh, *Hl, *W1h, *W1l, *W2h, *W2l;
    __nv_bfloat16 *QKVh, *QKVl;
    cudaGetSymbolAddress((void**)&Xh, g_Xh);
    cudaGetSymbolAddress((void**)&Xl, g_Xl);
    cudaGetSymbolAddress((void**)&Hh, g_Hh);
    cudaGetSymbolAddress((void**)&Hl, g_Hl);
    cudaGetSymbolAddress((void**)&W1h, g_W1h);
    cudaGetSymbolAddress((void**)&W1l, g_W1l);
    cudaGetSymbolAddress((void**)&W2h, g_W2h);
    cudaGetSymbolAddress((void**)&W2l, g_W2l);
    cudaGetSymbolAddress((void**)&QKVh, g_QKVh);
    cudaGetSymbolAddress((void**)&QKVl, g_QKVl);

    cudaFuncSetAttribute(mma_gemm_kernel<1>,
                         cudaFuncAttributeMaxDynamicSharedMemorySize, GEMM_SMEM);
    cudaFuncSetAttribute(mma_gemm_kernel<2>,
                         cudaFuncAttributeMaxDynamicSharedMemorySize, GEMM_SMEM);
    cudaFuncSetAttribute(attn_ln_kernel,
                         cudaFuncAttributeMaxDynamicSharedMemorySize, ATTN_SMEM);

    convert_x_kernel<<<(MT * DD) / (256 * 8), 256>>>(x, Xh, Xl);

    const dim3 gw(24, 24);
    const dim3 bw(32, 8);
    const float* W1[3] = {qw1, kw1, vw1};
    const float* W2[3] = {qw2, kw2, vw2};
    for (int m = 0; m < 3; m++) {
        convert_wt_kernel<<<gw, bw>>>(W1[m], W1h + (size_t)m * SZ_W, W1l + (size_t)m * SZ_W);
        convert_wt_kernel<<<gw, bw>>>(W2[m], W2h + (size_t)m * SZ_W, W2l + (size_t)m * SZ_W);
    }

    const dim3 gg(DD / 128, MT / 256, 3);   // (6, 64, 3)
    mma_gemm_kernel<1><<<gg, 512, GEMM_SMEM>>>(Xh, Xl, W1h, W1l,
                                               qb1, kb1, vb1, Hh, Hl);
    mma_gemm_kernel<2><<<gg, 512, GEMM_SMEM>>>(Hh, Hl, W2h, W2l,
                                               qb2, kb2, vb2,
                                               (uint8_t*)QKVh, (uint8_t*)QKVl);

    attn_ln_kernel<<<MT / TQ, 256, ATTN_SMEM>>>(
        QKVh, QKVl,
        QKVh + (size_t)MT * DD, QKVl + (size_t)MT * DD,
        QKVh + 2ull * MT * DD, QKVl + 2ull * MT * DD,
        lnw, lnb, out);
}

// round 7
// speedup vs baseline: 1.3234x; 1.0490x over previous
#include <cuda_runtime.h>
#include <cuda_bf16.h>
#include <math.h>
#include <stdint.h>

#define MT 16384
#define DD 768
#define NCH 12                       // K chunks of 64
#define A_PLANE (MT * 128)           // bytes per chunk plane (M=16384)
#define W_PLANE (DD * 128)           // bytes per chunk plane (M=768)
#define SZ_X ((size_t)MT * DD * 2)
#define SZ_W ((size_t)DD * DD * 2)
#define PAD_B 32768                  // 256 rows x 128B zero pad before QKV planes
#define SLOT (PAD_B + SZ_X)

// GEMM smem stage: Ah 32K | Al 32K | Bh 16K | Bl 16K
#define STG_AL 32768
#define STG_BH 65536
#define STG_BL 81920
#define STAGE  98304
#define GEMM_SMEM (2 * STAGE)

// ---- attention ----
#define TQ 32
#define SSTR 296
#define AT_SH 0
#define AT_SL 18944
#define AT_A  37888
#define AT_KH 0
#define AT_KL 36864
#define AT_QH 73728
#define AT_QL 77824
#define AT_P2S 32768                 // per-stage: VH 16384 | VL 16384
#define AT_Y  119808
#define ATTN_SMEM 218112

#define INV_SCALE 0.0022552744890219756f

// ---------------------------------------------------------------------------
__device__ __align__(128) uint8_t g_Xh[SZ_X];
__device__ __align__(128) uint8_t g_Xl[SZ_X];
__device__ __align__(128) uint8_t g_Hh[3 * SZ_X];
__device__ __align__(128) uint8_t g_Hl[3 * SZ_X];
__device__ __align__(128) uint8_t g_W1h[3 * SZ_W];
__device__ __align__(128) uint8_t g_W1l[3 * SZ_W];
__device__ __align__(128) uint8_t g_W2h[3 * SZ_W];
__device__ __align__(128) uint8_t g_W2l[3 * SZ_W];
__device__ __align__(128) uint8_t g_QKVh[3 * SLOT];   // zero-init pads
__device__ __align__(128) uint8_t g_QKVl[3 * SLOT];

__device__ __forceinline__ float gelu_exact(float x) {
    return 0.5f * x * (1.0f + erff(x * 0.70710678118654752f));
}
__device__ __forceinline__ uint32_t s2u(const void* p) {
    uint32_t a;
    asm("{ .reg .u64 t; cvta.to.shared.u64 t, %1; cvt.u32.u64 %0, t; }"
        : "=r"(a) : "l"(p));
    return a;
}
__device__ __forceinline__ size_t toff(int row, int k, size_t plane) {
    const int u = ((k >> 3) & 7) ^ (row & 7);
    return (size_t)(k >> 6) * plane + (size_t)row * 128 + (size_t)(u << 4) + (size_t)(k & 7) * 2;
}

// ---- primitives ----
__device__ __forceinline__ void mma_bf16(float* c, const uint32_t* a, const uint32_t* b) {
    asm volatile(
        "mma.sync.aligned.m16n8k16.row.col.f32.bf16.bf16.f32 "
        "{%0,%1,%2,%3}, {%4,%5,%6,%7}, {%8,%9}, {%0,%1,%2,%3};"
        : "+f"(c[0]), "+f"(c[1]), "+f"(c[2]), "+f"(c[3])
        : "r"(a[0]), "r"(a[1]), "r"(a[2]), "r"(a[3]), "r"(b[0]), "r"(b[1]));
}
__device__ __forceinline__ void ldsm_x4(uint32_t* r, uint32_t addr) {
    asm volatile("ldmatrix.sync.aligned.m8n8.x4.shared.b16 {%0,%1,%2,%3}, [%4];"
                 : "=r"(r[0]), "=r"(r[1]), "=r"(r[2]), "=r"(r[3]) : "r"(addr));
}
__device__ __forceinline__ void ldsm_x4_t(uint32_t* r, uint32_t addr) {
    asm volatile("ldmatrix.sync.aligned.m8n8.x4.trans.shared.b16 {%0,%1,%2,%3}, [%4];"
                 : "=r"(r[0]), "=r"(r[1]), "=r"(r[2]), "=r"(r[3]) : "r"(addr));
}
__device__ __forceinline__ void ldsm_x2(uint32_t* r, uint32_t addr) {
    asm volatile("ldmatrix.sync.aligned.m8n8.x2.shared.b16 {%0,%1}, [%2];"
                 : "=r"(r[0]), "=r"(r[1]) : "r"(addr));
}
#define MB_INIT(addr, cnt) \
    asm volatile("mbarrier.init.shared.b64 [%0], %1;" :: "r"(addr), "r"(cnt) : "memory")
#define MB_EXPECT(addr, tx) \
    asm volatile("mbarrier.arrive.expect_tx.shared.b64 _, [%0], %1;" :: "r"(addr), "r"(tx) : "memory")
#define BULK_G2S(dst, src, sz, mb) \
    asm volatile("cp.async.bulk.shared::cluster.global.mbarrier::complete_tx::bytes [%0], [%1], %2, [%3];" \
                 :: "r"(dst), "l"(src), "r"(sz), "r"(mb) : "memory")
#define MB_WAIT(addr, par) do {                                                \
    uint32_t _m = (addr), _p = (par), _d;                                      \
    asm volatile("{\n\t.reg .pred p;\n\t"                                      \
        "mbarrier.try_wait.parity.acquire.cta.shared::cta.b64 p, [%1], %2;\n\t"\
        "selp.b32 %0, 1, 0, p;\n\t}"                                           \
        : "=r"(_d) : "r"(_m), "r"(_p) : "memory");                             \
    if (!_d) {                                                                 \
        asm volatile("{\n\t.reg .pred P1;\n\t"                                 \
            "WL_%=:\n\t"                                                       \
            "mbarrier.try_wait.parity.acquire.cta.shared::cta.b64 P1, [%0], %1, 0x989680;\n\t" \
            "@P1 bra.uni WD_%=;\n\t"                                           \
            "bra.uni WL_%=;\n\t"                                               \
            "WD_%=:\n\t}"                                                      \
            :: "r"(_m), "r"(_p) : "memory");                                   \
    }                                                                          \
} while (0)

__device__ __forceinline__ uint32_t pack_hl(float v, float w, uint32_t& lo) {
    __nv_bfloat16 h0 = __float2bfloat16(v);
    __nv_bfloat16 h1 = __float2bfloat16(w);
    __nv_bfloat16 l0 = __float2bfloat16(v - __bfloat162float(h0));
    __nv_bfloat16 l1 = __float2bfloat16(w - __bfloat162float(h1));
    lo = (uint32_t)__bfloat16_as_ushort(l0) | ((uint32_t)__bfloat16_as_ushort(l1) << 16);
    return (uint32_t)__bfloat16_as_ushort(h0) | ((uint32_t)__bfloat16_as_ushort(h1) << 16);
}

// ---------------------------------------------------------------------------
__global__ void convert_x_kernel(const float* __restrict__ X,
                                 uint8_t* __restrict__ Xh,
                                 uint8_t* __restrict__ Xl) {
    const long gi = (long)(blockIdx.x * blockDim.x + threadIdx.x) * 8;
    const int row = (int)(gi / DD);
    const int k   = (int)(gi % DD);
    const float4 v0 = *(const float4*)(X + gi);
    const float4 v1 = *(const float4*)(X + gi + 4);
    uint32_t h[4], l[4];
    h[0] = pack_hl(v0.x, v0.y, l[0]);
    h[1] = pack_hl(v0.z, v0.w, l[1]);
    h[2] = pack_hl(v1.x, v1.y, l[2]);
    h[3] = pack_hl(v1.z, v1.w, l[3]);
    const size_t o = toff(row, k, A_PLANE);
    *(uint4*)(Xh + o) = make_uint4(h[0], h[1], h[2], h[3]);
    *(uint4*)(Xl + o) = make_uint4(l[0], l[1], l[2], l[3]);
}

__global__ void convert_wt_kernel(const float* __restrict__ W,
                                  uint8_t* __restrict__ Wth,
                                  uint8_t* __restrict__ Wtl) {
    __shared__ float tile[32][33];
    const int bx = blockIdx.x * 32;
    const int by = blockIdx.y * 32;
    const int tx = threadIdx.x, ty = threadIdx.y;
    for (int r = ty; r < 32; r += 8)
        tile[r][tx] = W[(size_t)(by + r) * DD + bx + tx];
    __syncthreads();
    for (int r = ty; r < 32; r += 8) {
        const float v = tile[tx][r];
        const __nv_bfloat16 h = __float2bfloat16(v);
        const __nv_bfloat16 l = __float2bfloat16(v - __bfloat162float(h));
        const size_t o = toff(bx + r, by + tx, W_PLANE);
        *(__nv_bfloat16*)(Wth + o) = h;
        *(__nv_bfloat16*)(Wtl + o) = l;
    }
}

// ---------------------------------------------------------------------------
// bf16x3 GEMM (round-6 proven).  LAYER 1 -> tiled H.  LAYER 2 -> tiled QKV.
// ---------------------------------------------------------------------------
template<int LAYER>
__global__ void __launch_bounds__(512) mma_gemm_kernel(
    const uint8_t* __restrict__ Abh, const uint8_t* __restrict__ Abl,
    const uint8_t* __restrict__ Bbh, const uint8_t* __restrict__ Bbl,
    const float* __restrict__ bias0, const float* __restrict__ bias1,
    const float* __restrict__ bias2,
    uint8_t* __restrict__ Ch, uint8_t* __restrict__ Cl)
{
    extern __shared__ char sm[];
    __shared__ uint64_t s_mbar[2];
    const uint32_t smb = s2u(sm);
    const uint32_t mb0 = s2u(&s_mbar[0]);

    const int t    = threadIdx.x;
    const int warp = t >> 5;
    const int lane = t & 31;
    const int wm   = warp & 7;
    const int wn   = warp >> 3;
    const int n0   = blockIdx.x * 128;
    const int m0   = blockIdx.y * 256;
    const int z    = blockIdx.z;

    const uint8_t* Ah = Abh + (LAYER == 2 ? (size_t)z * SZ_X : 0);
    const uint8_t* Al = Abl + (LAYER == 2 ? (size_t)z * SZ_X : 0);
    const uint8_t* Bh = Bbh + (size_t)z * SZ_W;
    const uint8_t* Bl = Bbl + (size_t)z * SZ_W;
    const float* bias = (z == 0) ? bias0 : (z == 1) ? bias1 : bias2;

    if (t == 0) { MB_INIT(mb0, 1); MB_INIT(mb0 + 8, 1); }
    __syncthreads();

    auto load_chunk = [&](int c, int s) {
        if (t == 0) {
            const uint32_t sb = smb + s * STAGE;
            const uint32_t mb = mb0 + s * 8;
            MB_EXPECT(mb, STAGE);
            BULK_G2S(sb,          Ah + (size_t)c * A_PLANE + (size_t)m0 * 128, 32768, mb);
            BULK_G2S(sb + STG_AL, Al + (size_t)c * A_PLANE + (size_t)m0 * 128, 32768, mb);
            BULK_G2S(sb + STG_BH, Bh + (size_t)c * W_PLANE + (size_t)n0 * 128, 16384, mb);
            BULK_G2S(sb + STG_BL, Bl + (size_t)c * W_PLANE + (size_t)n0 * 128, 16384, mb);
        }
    };

    const int l15   = lane & 15;
    const int uA    = lane >> 4;
    const int q3    = lane >> 3;
    const int brl   = lane & 7;
    const int brow  = (q3 < 2) ? brl : (8 + brl);
    const int uB    = q3 & 1;

    float acc[2][8][4];
    #pragma unroll
    for (int i = 0; i < 2; i++)
        #pragma unroll
        for (int j = 0; j < 8; j++)
            #pragma unroll
            for (int r = 0; r < 4; r++) acc[i][j][r] = 0.f;

    load_chunk(0, 0);
    int ph[2] = {0, 0};

    for (int c = 0; c < NCH; ++c) {
        const int s = c & 1;
        if (c + 1 < NCH) load_chunk(c + 1, s ^ 1);
        MB_WAIT(mb0 + s * 8, ph[s]);
        ph[s] ^= 1;

        const uint32_t sb = smb + s * STAGE;
        #pragma unroll
        for (int k16 = 0; k16 < 64; k16 += 16) {
            uint32_t ah[2][4], al[2][4];
            #pragma unroll
            for (int mt = 0; mt < 2; mt++) {
                const int row = wm * 32 + mt * 16 + l15;
                const int u   = ((k16 >> 3) + uA) ^ (row & 7);
                const uint32_t ao = (uint32_t)(row * 128 + (u << 4));
                ldsm_x4(ah[mt], sb + ao);
                ldsm_x4(al[mt], sb + STG_AL + ao);
            }
            #pragma unroll
            for (int p = 0; p < 4; p++) {
                const int row = wn * 64 + p * 16 + brow;
                const int u   = ((k16 >> 3) + uB) ^ (row & 7);
                const uint32_t bo = (uint32_t)(row * 128 + (u << 4));
                uint32_t rh[4], rl[4];
                ldsm_x4(rh, sb + STG_BH + bo);
                ldsm_x4(rl, sb + STG_BL + bo);
                #pragma unroll
                for (int h = 0; h < 2; h++) {
                    const int nt = 2 * p + h;
                    #pragma unroll
                    for (int mt = 0; mt < 2; mt++) {
                        mma_bf16(acc[mt][nt], ah[mt], rh + 2 * h);
                        mma_bf16(acc[mt][nt], ah[mt], rl + 2 * h);
                        mma_bf16(acc[mt][nt], al[mt], rh + 2 * h);
                    }
                }
            }
        }
        __syncthreads();
    }

    const int gid = lane >> 2;
    const int qid = lane & 3;
    #pragma unroll
    for (int mt = 0; mt < 2; mt++) {
        #pragma unroll
        for (int nt = 0; nt < 8; nt++) {
            const int col = n0 + wn * 64 + nt * 8 + qid * 2;
            const float b0 = bias[col], b1 = bias[col + 1];
            #pragma unroll
            for (int half = 0; half < 2; half++) {
                const int row = m0 + wm * 32 + mt * 16 + gid + half * 8;
                float v0 = acc[mt][nt][half * 2]     + b0;
                float v1 = acc[mt][nt][half * 2 + 1] + b1;
                if (LAYER == 1) { v0 = gelu_exact(v0); v1 = gelu_exact(v1); }
                uint32_t lo;
                const uint32_t hi = pack_hl(v0, v1, lo);
                if (LAYER == 1) {
                    const size_t o = (size_t)z * SZ_X + toff(row, col, A_PLANE);
                    *(uint32_t*)(Ch + o) = hi;
                    *(uint32_t*)(Cl + o) = lo;
                } else {
                    const size_t o = (size_t)z * SLOT + PAD_B + toff(row, col, A_PLANE);
                    *(uint32_t*)(Ch + o) = hi;
                    *(uint32_t*)(Cl + o) = lo;
                }
            }
        }
    }
}

// ---------------------------------------------------------------------------
// Fused banded attention + LayerNorm, bulk-copy edition.
// Inputs are tiled-planar with PAD_B already applied to the pointers.
// ---------------------------------------------------------------------------
__global__ void __launch_bounds__(256) attn_ln_kernel(
    const uint8_t* __restrict__ Qh, const uint8_t* __restrict__ Ql,
    const uint8_t* __restrict__ Kh, const uint8_t* __restrict__ Kl,
    const uint8_t* __restrict__ Vh, const uint8_t* __restrict__ Vl,
    const float* __restrict__ lnw, const float* __restrict__ lnb,
    float* __restrict__ out)
{
    extern __shared__ char smc[];
    __shared__ uint64_t s_mb[3];
    const uint32_t smb = s2u(smc);
    const uint32_t smA = smb + AT_A;
    float* Ysh = (float*)(smc + AT_Y);
    const uint32_t mb = s2u(&s_mb[0]);

    const int t    = threadIdx.x;
    const int warp = t >> 5;
    const int lane = t & 31;
    const int wm   = warp >> 2;
    const int wn   = warp & 3;
    const int gid  = lane >> 2;
    const int qid  = lane & 3;

    const int bx = blockIdx.x;
    const int b  = bx >> 7;
    const int i0 = (bx & 127) * TQ;
    const long base = (long)b * 4096;
    const long gq   = base + i0;          // Q rows
    const long gk   = base + i0 - 256;    // band start (may be < 0 for b=0 only)
    const int jb = i0 - 256;

    const int l15  = lane & 15;
    const int uA   = lane >> 4;
    const int q3   = lane >> 3;
    const int brl  = lane & 7;
    const int brow = (q3 < 2) ? brl : (8 + brl);
    const int uB   = q3 & 1;

    if (t == 0) { MB_INIT(mb, 1); MB_INIT(mb + 8, 1); MB_INIT(mb + 16, 1); }
    __syncthreads();

    // =================== phase 1: S = mask(Q @ K^T) ===================
    auto p1_load = [&](int c) {
        if (t == 0) {
            MB_EXPECT(mb, 81920);
            BULK_G2S(smA + AT_KH, Kh + ((long)c * A_PLANE + gk * 128), 36864, mb);
            BULK_G2S(smA + AT_KL, Kl + ((long)c * A_PLANE + gk * 128), 36864, mb);
            BULK_G2S(smA + AT_QH, Qh + ((long)c * A_PLANE + gq * 128), 4096, mb);
            BULK_G2S(smA + AT_QL, Ql + ((long)c * A_PLANE + gq * 128), 4096, mb);
        }
    };

    float acc[9][4];
    #pragma unroll
    for (int n = 0; n < 9; n++)
        #pragma unroll
        for (int r = 0; r < 4; r++) acc[n][r] = 0.f;

    p1_load(0);
    int ph0 = 0;

    for (int c = 0; c < NCH; ++c) {
        MB_WAIT(mb, ph0);
        ph0 ^= 1;

        #pragma unroll
        for (int k16 = 0; k16 < 64; k16 += 16) {
            uint32_t ah[4], al[4];
            {
                const int row = wm * 16 + l15;
                const int u   = ((k16 >> 3) + uA) ^ (row & 7);
                const uint32_t ao = (uint32_t)(row * 128 + (u << 4));
                ldsm_x4(ah, smA + AT_QH + ao);
                ldsm_x4(al, smA + AT_QL + ao);
            }
            uint32_t bh[9][2], bl[9][2];
            #pragma unroll
            for (int p = 0; p < 4; p++) {
                const int row = wn * 72 + p * 16 + brow;
                const int u   = ((k16 >> 3) + uB) ^ (row & 7);
                const uint32_t bo = (uint32_t)(row * 128 + (u << 4));
                uint32_t r4[4];
                ldsm_x4(r4, smA + AT_KH + bo);
                bh[2*p][0] = r4[0]; bh[2*p][1] = r4[1];
                bh[2*p+1][0] = r4[2]; bh[2*p+1][1] = r4[3];
                ldsm_x4(r4, smA + AT_KL + bo);
                bl[2*p][0] = r4[0]; bl[2*p][1] = r4[1];
                bl[2*p+1][0] = r4[2]; bl[2*p+1][1] = r4[3];
            }
            {
                const int row = wn * 72 + 64 + brl;
                const int u   = ((k16 >> 3) + ((lane >> 3) & 1)) ^ (row & 7);
                const uint32_t bo = (uint32_t)(row * 128 + (u << 4));
                ldsm_x2(bh[8], smA + AT_KH + bo);
                ldsm_x2(bl[8], smA + AT_KL + bo);
            }
            #pragma unroll
            for (int nt = 0; nt < 9; nt++) {
                mma_bf16(acc[nt], ah, bh[nt]);
                mma_bf16(acc[nt], ah, bl[nt]);
                mma_bf16(acc[nt], al, bh[nt]);
            }
        }
        __syncthreads();
        if (c + 1 < NCH) p1_load(c + 1);
    }

    // mask + scale + split hi/lo into S smem
    #pragma unroll
    for (int nt = 0; nt < 9; nt++) {
        const int jw0 = wn * 72 + nt * 8 + qid * 2;
        #pragma unroll
        for (int half = 0; half < 2; half++) {
            const int ti = wm * 16 + gid + half * 8;
            float v0 = acc[nt][half * 2];
            float v1 = acc[nt][half * 2 + 1];
            const bool ok0 = (jb + jw0     >= 0) && (jw0     > ti) && (jw0     <= ti + 256);
            const bool ok1 = (jb + jw0 + 1 >= 0) && (jw0 + 1 > ti) && (jw0 + 1 <= ti + 256);
            v0 = ok0 ? v0 * INV_SCALE : 0.f;
            v1 = ok1 ? v1 * INV_SCALE : 0.f;
            uint32_t lo;
            const uint32_t hi = pack_hl(v0, v1, lo);
            const uint32_t so = (uint32_t)(ti * SSTR + jw0) * 2;
            *(uint32_t*)(smc + AT_SH + so) = hi;
            *(uint32_t*)(smc + AT_SL + so) = lo;
        }
    }
    __syncthreads();

    // =================== phase 2: Y = S @ V ===================
    auto p2_load = [&](int iter, int s) {
        if (t == 0) {
            const int dc = iter / 9;
            const int js = iter % 9;
            const long r0 = gk + js * 32;
            const uint32_t sb = smA + s * AT_P2S;
            const uint32_t m2 = mb + 8 + s * 8;
            MB_EXPECT(m2, 32768);
            #pragma unroll
            for (int q = 0; q < 4; q++) {
                const int cv = dc * 4 + q;
                BULK_G2S(sb + q * 4096,         Vh + ((long)cv * A_PLANE + r0 * 128), 4096, m2);
                BULK_G2S(sb + 16384 + q * 4096, Vl + ((long)cv * A_PLANE + r0 * 128), 4096, m2);
            }
        }
    };

    float acc2[8][4];
    #pragma unroll
    for (int n = 0; n < 8; n++)
        #pragma unroll
        for (int r = 0; r < 4; r++) acc2[n][r] = 0.f;

    p2_load(0, 0);
    p2_load(1, 1);
    int ph2[2] = {0, 0};

    for (int iter = 0; iter < 27; ++iter) {
        const int s = iter & 1;
        MB_WAIT(mb + 8 + s * 8, ph2[s]);
        ph2[s] ^= 1;

        const int js = (iter % 9) * 32;
        const uint32_t sb = smA + s * AT_P2S;
        #pragma unroll
        for (int k16 = 0; k16 < 32; k16 += 16) {
            uint32_t ah[4], al[4];
            const uint32_t ao = (uint32_t)((wm * 16 + l15) * SSTR + js + k16 + uA * 8) * 2;
            ldsm_x4(ah, smb + AT_SH + ao);
            ldsm_x4(al, smb + AT_SL + ao);

            uint32_t bh[8][2], bl[8][2];
            #pragma unroll
            for (int p = 0; p < 4; p++) {
                const int row = k16 + l15;                 // j within 32
                const int u   = (2 * p + uA) ^ (row & 7);  // col unit within chunk
                const uint32_t bo = (uint32_t)(wn * 4096 + row * 128 + (u << 4));
                uint32_t r4[4];
                ldsm_x4_t(r4, sb + bo);
                bh[2*p][0] = r4[0]; bh[2*p][1] = r4[1];
                bh[2*p+1][0] = r4[2]; bh[2*p+1][1] = r4[3];
                ldsm_x4_t(r4, sb + 16384 + bo);
                bl[2*p][0] = r4[0]; bl[2*p][1] = r4[1];
                bl[2*p+1][0] = r4[2]; bl[2*p+1][1] = r4[3];
            }
            #pragma unroll
            for (int nt = 0; nt < 8; nt++) {
                mma_bf16(acc2[nt], ah, bh[nt]);
                mma_bf16(acc2[nt], ah, bl[nt]);
                mma_bf16(acc2[nt], al, bh[nt]);
            }
        }

        if ((iter % 9) == 8) {
            const int dc = (iter / 9) * 256;
            #pragma unroll
            for (int nt = 0; nt < 8; nt++) {
                const int col = dc + wn * 64 + nt * 8 + qid * 2;
                #pragma unroll
                for (int half = 0; half < 2; half++) {
                    const int row = wm * 16 + gid + half * 8;
                    *(float2*)&Ysh[row * DD + col] =
                        make_float2(acc2[nt][half * 2], acc2[nt][half * 2 + 1]);
                }
            }
            #pragma unroll
            for (int n = 0; n < 8; n++)
                #pragma unroll
                for (int r = 0; r < 4; r++) acc2[n][r] = 0.f;
        }
        __syncthreads();
        if (iter + 2 < 27) p2_load(iter + 2, s);
    }

    // =================== phase 3: LayerNorm ===================
    #pragma unroll
    for (int rr = 0; rr < 4; rr++) {
        const int row = warp * 4 + rr;
        float s = 0.f, ss = 0.f;
        #pragma unroll
        for (int c0 = 0; c0 < DD; c0 += 32) {
            const float y = Ysh[row * DD + c0 + lane];
            s += y; ss += y * y;
        }
        #pragma unroll
        for (int o = 16; o > 0; o >>= 1) {
            s  += __shfl_xor_sync(0xffffffffu, s,  o);
            ss += __shfl_xor_sync(0xffffffffu, ss, o);
        }
        const float mu   = s * (1.f / 768.f);
        const float var  = ss * (1.f / 768.f) - mu * mu;
        const float rstd = rsqrtf(var + 1e-5f);
        #pragma unroll
        for (int c0 = 0; c0 < DD; c0 += 32) {
            const int c = c0 + lane;
            const float y = Ysh[row * DD + c];
            out[(base + i0 + row) * DD + c] = (y - mu) * rstd * lnw[c] + lnb[c];
        }
    }
}

// ---------------------------------------------------------------------------
extern "C" void kernel_launch(void* const* d_in, const int* in_sizes, int n_in,
                              void* d_out, int out_size)
{
    const float* x   = (const float*)d_in[0];
    const float* qw1 = (const float*)d_in[1];
    const float* qb1 = (const float*)d_in[2];
    const float* qw2 = (const float*)d_in[3];
    const float* qb2 = (const float*)d_in[4];
    const float* kw1 = (const float*)d_in[5];
    const float* kb1 = (const float*)d_in[6];
    const float* kw2 = (const float*)d_in[7];
    const float* kb2 = (const float*)d_in[8];
    const float* vw1 = (const float*)d_in[9];
    const float* vb1 = (const float*)d_in[10];
    const float* vw2 = (const float*)d_in[11];
    const float* vb2 = (const float*)d_in[12];
    const float* lnw = (const float*)d_in[13];
    const float* lnb = (const float*)d_in[14];
    float* out = (float*)d_out;

    uint8_t *Xh, *Xl, *Hh, *Hl, *W1h, *W1l, *W2h, *W2l, *QKVh, *QKVl;
    cudaGetSymbolAddress((void**)&Xh, g_Xh);
    cudaGetSymbolAddress((void**)&Xl, g_Xl);
    cudaGetSymbolAddress((void**)&Hh, g_Hh);
    cudaGetSymbolAddress((void**)&Hl, g_Hl);
    cudaGetSymbolAddress((void**)&W1h, g_W1h);
    cudaGetSymbolAddress((void**)&W1l, g_W1l);
    cudaGetSymbolAddress((void**)&W2h, g_W2h);
    cudaGetSymbolAddress((void**)&W2l, g_W2l);
    cudaGetSymbolAddress((void**)&QKVh, g_QKVh);
    cudaGetSymbolAddress((void**)&QKVl, g_QKVl);

    cudaFuncSetAttribute(mma_gemm_kernel<1>,
                         cudaFuncAttributeMaxDynamicSharedMemorySize, GEMM_SMEM);
    cudaFuncSetAttribute(mma_gemm_kernel<2>,
                         cudaFuncAttributeMaxDynamicSharedMemorySize, GEMM_SMEM);
    cudaFuncSetAttribute(attn_ln_kernel,
                         cudaFuncAttributeMaxDynamicSharedMemorySize, ATTN_SMEM);

    convert_x_kernel<<<(MT * DD) / (256 * 8), 256>>>(x, Xh, Xl);

    const dim3 gw(24, 24);
    const dim3 bw(32, 8);
    const float* W1[3] = {qw1, kw1, vw1};
    const float* W2[3] = {qw2, kw2, vw2};
    for (int m = 0; m < 3; m++) {
        convert_wt_kernel<<<gw, bw>>>(W1[m], W1h + (size_t)m * SZ_W, W1l + (size_t)m * SZ_W);
        convert_wt_kernel<<<gw, bw>>>(W2[m], W2h + (size_t)m * SZ_W, W2l + (size_t)m * SZ_W);
    }

    const dim3 gg(DD / 128, MT / 256, 3);
    mma_gemm_kernel<1><<<gg, 512, GEMM_SMEM>>>(Xh, Xl, W1h, W1l,
                                               qb1, kb1, vb1, Hh, Hl);
    mma_gemm_kernel<2><<<gg, 512, GEMM_SMEM>>>(Hh, Hl, W2h, W2l,
                                               qb2, kb2, vb2, QKVh, QKVl);

    attn_ln_kernel<<<MT / TQ, 256, ATTN_SMEM>>>(
        QKVh + PAD_B,            QKVl + PAD_B,
        QKVh + SLOT + PAD_B,     QKVl + SLOT + PAD_B,
        QKVh + 2ull * SLOT + PAD_B, QKVl + 2ull * SLOT + PAD_B,
        lnw, lnb, out);
}

// round 8
// speedup vs baseline: 1.5061x; 1.1380x over previous
#include <cuda_runtime.h>
#include <cuda_bf16.h>
#include <math.h>
#include <stdint.h>

#define MT 16384
#define DD 768
#define NCH 12                       // K chunks of 64
#define A_PLANE (MT * 128)           // bytes per chunk plane (M=16384)
#define W_PLANE (DD * 128)           // bytes per chunk plane (M=768)
#define SZ_X ((size_t)MT * DD * 2)
#define SZ_W ((size_t)DD * DD * 2)
#define PAD_B 32768                  // 256 rows x 128B zero pad before QKV planes
#define SLOT (PAD_B + SZ_X)

// GEMM smem stage: Ah 32K | Al 32K | Bh 16K | Bl 16K
#define STG_AL 32768
#define STG_BH 65536
#define STG_BL 81920
#define STAGE  98304
#define GEMM_SMEM (2 * STAGE)

// ---- attention ----
#define TQ 32
#define SSTR 296
#define AT_SH 0
#define AT_SL 18944
#define AT_A  37888
#define P1_STG 81920                 // per stage: KH 36864 | KL 36864 | QH 4096 | QL 4096
#define AT_KH 0
#define AT_KL 36864
#define AT_QH 73728
#define AT_QL 77824
#define AT_P2S 32768                 // per-stage: VH 16384 | VL 16384
#define ATTN_SMEM 201728             // AT_A + 2*P1_STG

#define INV_SCALE 0.0022552744890219756f

// ---------------------------------------------------------------------------
__device__ __align__(128) uint8_t g_Xh[SZ_X];
__device__ __align__(128) uint8_t g_Xl[SZ_X];
__device__ __align__(128) uint8_t g_Hh[3 * SZ_X];
__device__ __align__(128) uint8_t g_Hl[3 * SZ_X];
__device__ __align__(128) uint8_t g_W1h[3 * SZ_W];
__device__ __align__(128) uint8_t g_W1l[3 * SZ_W];
__device__ __align__(128) uint8_t g_W2h[3 * SZ_W];
__device__ __align__(128) uint8_t g_W2l[3 * SZ_W];
__device__ __align__(128) uint8_t g_QKVh[3 * SLOT];   // zero-init pads
__device__ __align__(128) uint8_t g_QKVl[3 * SLOT];
__device__ float g_Y[(size_t)MT * DD];

__device__ __forceinline__ float gelu_exact(float x) {
    return 0.5f * x * (1.0f + erff(x * 0.70710678118654752f));
}
__device__ __forceinline__ uint32_t s2u(const void* p) {
    uint32_t a;
    asm("{ .reg .u64 t; cvta.to.shared.u64 t, %1; cvt.u32.u64 %0, t; }"
        : "=r"(a) : "l"(p));
    return a;
}
__device__ __forceinline__ size_t toff(int row, int k, size_t plane) {
    const int u = ((k >> 3) & 7) ^ (row & 7);
    return (size_t)(k >> 6) * plane + (size_t)row * 128 + (size_t)(u << 4) + (size_t)(k & 7) * 2;
}

// ---- primitives ----
__device__ __forceinline__ void mma_bf16(float* c, const uint32_t* a, const uint32_t* b) {
    asm volatile(
        "mma.sync.aligned.m16n8k16.row.col.f32.bf16.bf16.f32 "
        "{%0,%1,%2,%3}, {%4,%5,%6,%7}, {%8,%9}, {%0,%1,%2,%3};"
        : "+f"(c[0]), "+f"(c[1]), "+f"(c[2]), "+f"(c[3])
        : "r"(a[0]), "r"(a[1]), "r"(a[2]), "r"(a[3]), "r"(b[0]), "r"(b[1]));
}
__device__ __forceinline__ void ldsm_x4(uint32_t* r, uint32_t addr) {
    asm volatile("ldmatrix.sync.aligned.m8n8.x4.shared.b16 {%0,%1,%2,%3}, [%4];"
                 : "=r"(r[0]), "=r"(r[1]), "=r"(r[2]), "=r"(r[3]) : "r"(addr));
}
__device__ __forceinline__ void ldsm_x4_t(uint32_t* r, uint32_t addr) {
    asm volatile("ldmatrix.sync.aligned.m8n8.x4.trans.shared.b16 {%0,%1,%2,%3}, [%4];"
                 : "=r"(r[0]), "=r"(r[1]), "=r"(r[2]), "=r"(r[3]) : "r"(addr));
}
__device__ __forceinline__ void ldsm_x2(uint32_t* r, uint32_t addr) {
    asm volatile("ldmatrix.sync.aligned.m8n8.x2.shared.b16 {%0,%1}, [%2];"
                 : "=r"(r[0]), "=r"(r[1]) : "r"(addr));
}
#define MB_INIT(addr, cnt) \
    asm volatile("mbarrier.init.shared.b64 [%0], %1;" :: "r"(addr), "r"(cnt) : "memory")
#define MB_EXPECT(addr, tx) \
    asm volatile("mbarrier.arrive.expect_tx.shared.b64 _, [%0], %1;" :: "r"(addr), "r"(tx) : "memory")
#define MB_ARRIVE(addr) \
    asm volatile("mbarrier.arrive.shared.b64 _, [%0];" :: "r"(addr) : "memory")
#define BULK_G2S(dst, src, sz, mb) \
    asm volatile("cp.async.bulk.shared::cluster.global.mbarrier::complete_tx::bytes [%0], [%1], %2, [%3];" \
                 :: "r"(dst), "l"(src), "r"(sz), "r"(mb) : "memory")
#define MB_WAIT(addr, par) do {                                                \
    uint32_t _m = (addr), _p = (par), _d;                                      \
    asm volatile("{\n\t.reg .pred p;\n\t"                                      \
        "mbarrier.try_wait.parity.acquire.cta.shared::cta.b64 p, [%1], %2;\n\t"\
        "selp.b32 %0, 1, 0, p;\n\t}"                                           \
        : "=r"(_d) : "r"(_m), "r"(_p) : "memory");                             \
    if (!_d) {                                                                 \
        asm volatile("{\n\t.reg .pred P1;\n\t"                                 \
            "WL_%=:\n\t"                                                       \
            "mbarrier.try_wait.parity.acquire.cta.shared::cta.b64 P1, [%0], %1, 0x989680;\n\t" \
            "@P1 bra.uni WD_%=;\n\t"                                           \
            "bra.uni WL_%=;\n\t"                                               \
            "WD_%=:\n\t}"                                                      \
            :: "r"(_m), "r"(_p) : "memory");                                   \
    }                                                                          \
} while (0)

__device__ __forceinline__ uint32_t pack_hl(float v, float w, uint32_t& lo) {
    __nv_bfloat16 h0 = __float2bfloat16(v);
    __nv_bfloat16 h1 = __float2bfloat16(w);
    __nv_bfloat16 l0 = __float2bfloat16(v - __bfloat162float(h0));
    __nv_bfloat16 l1 = __float2bfloat16(w - __bfloat162float(h1));
    lo = (uint32_t)__bfloat16_as_ushort(l0) | ((uint32_t)__bfloat16_as_ushort(l1) << 16);
    return (uint32_t)__bfloat16_as_ushort(h0) | ((uint32_t)__bfloat16_as_ushort(h1) << 16);
}

// ---------------------------------------------------------------------------
__global__ void convert_x_kernel(const float* __restrict__ X,
                                 uint8_t* __restrict__ Xh,
                                 uint8_t* __restrict__ Xl) {
    const long gi = (long)(blockIdx.x * blockDim.x + threadIdx.x) * 8;
    const int row = (int)(gi / DD);
    const int k   = (int)(gi % DD);
    const float4 v0 = *(const float4*)(X + gi);
    const float4 v1 = *(const float4*)(X + gi + 4);
    uint32_t h[4], l[4];
    h[0] = pack_hl(v0.x, v0.y, l[0]);
    h[1] = pack_hl(v0.z, v0.w, l[1]);
    h[2] = pack_hl(v1.x, v1.y, l[2]);
    h[3] = pack_hl(v1.z, v1.w, l[3]);
    const size_t o = toff(row, k, A_PLANE);
    *(uint4*)(Xh + o) = make_uint4(h[0], h[1], h[2], h[3]);
    *(uint4*)(Xl + o) = make_uint4(l[0], l[1], l[2], l[3]);
}

__global__ void convert_wt_kernel(const float* __restrict__ W,
                                  uint8_t* __restrict__ Wth,
                                  uint8_t* __restrict__ Wtl) {
    __shared__ float tile[32][33];
    const int bx = blockIdx.x * 32;
    const int by = blockIdx.y * 32;
    const int tx = threadIdx.x, ty = threadIdx.y;
    for (int r = ty; r < 32; r += 8)
        tile[r][tx] = W[(size_t)(by + r) * DD + bx + tx];
    __syncthreads();
    for (int r = ty; r < 32; r += 8) {
        const float v = tile[tx][r];
        const __nv_bfloat16 h = __float2bfloat16(v);
        const __nv_bfloat16 l = __float2bfloat16(v - __bfloat162float(h));
        const size_t o = toff(bx + r, by + tx, W_PLANE);
        *(__nv_bfloat16*)(Wth + o) = h;
        *(__nv_bfloat16*)(Wtl + o) = l;
    }
}

// ---------------------------------------------------------------------------
// bf16x3 GEMM; mainloop sync via producer/consumer mbarriers (no syncthreads).
// ---------------------------------------------------------------------------
template<int LAYER>
__global__ void __launch_bounds__(512) mma_gemm_kernel(
    const uint8_t* __restrict__ Abh, const uint8_t* __restrict__ Abl,
    const uint8_t* __restrict__ Bbh, const uint8_t* __restrict__ Bbl,
    const float* __restrict__ bias0, const float* __restrict__ bias1,
    const float* __restrict__ bias2,
    uint8_t* __restrict__ Ch, uint8_t* __restrict__ Cl)
{
    extern __shared__ char sm[];
    __shared__ uint64_t s_mbar[4];   // full0, full1, empty0, empty1
    const uint32_t smb = s2u(sm);
    const uint32_t mb0 = s2u(&s_mbar[0]);

    const int t    = threadIdx.x;
    const int warp = t >> 5;
    const int lane = t & 31;
    const int wm   = warp & 7;
    const int wn   = warp >> 3;
    const int n0   = blockIdx.x * 128;
    const int m0   = blockIdx.y * 256;
    const int z    = blockIdx.z;

    const uint8_t* Ah = Abh + (LAYER == 2 ? (size_t)z * SZ_X : 0);
    const uint8_t* Al = Abl + (LAYER == 2 ? (size_t)z * SZ_X : 0);
    const uint8_t* Bh = Bbh + (size_t)z * SZ_W;
    const uint8_t* Bl = Bbl + (size_t)z * SZ_W;
    const float* bias = (z == 0) ? bias0 : (z == 1) ? bias1 : bias2;

    if (t == 0) {
        MB_INIT(mb0, 1);  MB_INIT(mb0 + 8, 1);
        MB_INIT(mb0 + 16, 16);  MB_INIT(mb0 + 24, 16);
    }
    __syncthreads();

    auto load_chunk = [&](int c, int s) {
        const uint32_t sb = smb + s * STAGE;
        const uint32_t mb = mb0 + s * 8;
        MB_EXPECT(mb, STAGE);
        BULK_G2S(sb,          Ah + (size_t)c * A_PLANE + (size_t)m0 * 128, 32768, mb);
        BULK_G2S(sb + STG_AL, Al + (size_t)c * A_PLANE + (size_t)m0 * 128, 32768, mb);
        BULK_G2S(sb + STG_BH, Bh + (size_t)c * W_PLANE + (size_t)n0 * 128, 16384, mb);
        BULK_G2S(sb + STG_BL, Bl + (size_t)c * W_PLANE + (size_t)n0 * 128, 16384, mb);
    };

    const int l15   = lane & 15;
    const int uA    = lane >> 4;
    const int q3    = lane >> 3;
    const int brl   = lane & 7;
    const int brow  = (q3 < 2) ? brl : (8 + brl);
    const int uB    = q3 & 1;

    float acc[2][8][4];
    #pragma unroll
    for (int i = 0; i < 2; i++)
        #pragma unroll
        for (int j = 0; j < 8; j++)
            #pragma unroll
            for (int r = 0; r < 4; r++) acc[i][j][r] = 0.f;

    if (t == 0) load_chunk(0, 0);
    int pf[2] = {0, 0}, pe[2] = {0, 0};

    for (int c = 0; c < NCH; ++c) {
        const int s = c & 1;
        if (c + 1 < NCH && t == 0) {
            if (c >= 1) { MB_WAIT(mb0 + 16 + (s ^ 1) * 8, pe[s ^ 1]); pe[s ^ 1] ^= 1; }
            load_chunk(c + 1, s ^ 1);
        }
        MB_WAIT(mb0 + s * 8, pf[s]);
        pf[s] ^= 1;

        const uint32_t sb = smb + s * STAGE;
        #pragma unroll
        for (int k16 = 0; k16 < 64; k16 += 16) {
            uint32_t ah[2][4], al[2][4];
            #pragma unroll
            for (int mt = 0; mt < 2; mt++) {
                const int row = wm * 32 + mt * 16 + l15;
                const int u   = ((k16 >> 3) + uA) ^ (row & 7);
                const uint32_t ao = (uint32_t)(row * 128 + (u << 4));
                ldsm_x4(ah[mt], sb + ao);
                ldsm_x4(al[mt], sb + STG_AL + ao);
            }
            #pragma unroll
            for (int p = 0; p < 4; p++) {
                const int row = wn * 64 + p * 16 + brow;
                const int u   = ((k16 >> 3) + uB) ^ (row & 7);
                const uint32_t bo = (uint32_t)(row * 128 + (u << 4));
                uint32_t rh[4], rl[4];
                ldsm_x4(rh, sb + STG_BH + bo);
                ldsm_x4(rl, sb + STG_BL + bo);
                #pragma unroll
                for (int h = 0; h < 2; h++) {
                    const int nt = 2 * p + h;
                    #pragma unroll
                    for (int mt = 0; mt < 2; mt++) {
                        mma_bf16(acc[mt][nt], ah[mt], rh + 2 * h);
                        mma_bf16(acc[mt][nt], ah[mt], rl + 2 * h);
                        mma_bf16(acc[mt][nt], al[mt], rh + 2 * h);
                    }
                }
            }
        }
        if (lane == 0) MB_ARRIVE(mb0 + 16 + s * 8);
    }

    const int gid = lane >> 2;
    const int qid = lane & 3;
    #pragma unroll
    for (int mt = 0; mt < 2; mt++) {
        #pragma unroll
        for (int nt = 0; nt < 8; nt++) {
            const int col = n0 + wn * 64 + nt * 8 + qid * 2;
            const float b0 = bias[col], b1 = bias[col + 1];
            #pragma unroll
            for (int half = 0; half < 2; half++) {
                const int row = m0 + wm * 32 + mt * 16 + gid + half * 8;
                float v0 = acc[mt][nt][half * 2]     + b0;
                float v1 = acc[mt][nt][half * 2 + 1] + b1;
                if (LAYER == 1) { v0 = gelu_exact(v0); v1 = gelu_exact(v1); }
                uint32_t lo;
                const uint32_t hi = pack_hl(v0, v1, lo);
                if (LAYER == 1) {
                    const size_t o = (size_t)z * SZ_X + toff(row, col, A_PLANE);
                    *(uint32_t*)(Ch + o) = hi;
                    *(uint32_t*)(Cl + o) = lo;
                } else {
                    const size_t o = (size_t)z * SLOT + PAD_B + toff(row, col, A_PLANE);
                    *(uint32_t*)(Ch + o) = hi;
                    *(uint32_t*)(Cl + o) = lo;
                }
            }
        }
    }
}

// ---------------------------------------------------------------------------
// Banded attention (Q@K^T masked, S@V), Y -> gmem fp32. LN is separate.
// Phase 1 double-buffered.
// ---------------------------------------------------------------------------
__global__ void __launch_bounds__(256) attn_kernel(
    const uint8_t* __restrict__ Qh, const uint8_t* __restrict__ Ql,
    const uint8_t* __restrict__ Kh, const uint8_t* __restrict__ Kl,
    const uint8_t* __restrict__ Vh, const uint8_t* __restrict__ Vl,
    float* __restrict__ Y)
{
    extern __shared__ char smc[];
    __shared__ uint64_t s_mb[4];     // p1f0, p1f1, p2f0, p2f1
    const uint32_t smb = s2u(smc);
    const uint32_t smA = smb + AT_A;
    const uint32_t mb = s2u(&s_mb[0]);

    const int t    = threadIdx.x;
    const int warp = t >> 5;
    const int lane = t & 31;
    const int wm   = warp >> 2;
    const int wn   = warp & 3;
    const int gid  = lane >> 2;
    const int qid  = lane & 3;

    const int bx = blockIdx.x;
    const int b  = bx >> 7;
    const int i0 = (bx & 127) * TQ;
    const long base = (long)b * 4096;
    const long gq   = base + i0;
    const long gk   = base + i0 - 256;
    const int jb = i0 - 256;

    const int l15  = lane & 15;
    const int uA   = lane >> 4;
    const int q3   = lane >> 3;
    const int brl  = lane & 7;
    const int brow = (q3 < 2) ? brl : (8 + brl);
    const int uB   = q3 & 1;

    if (t == 0) {
        MB_INIT(mb, 1); MB_INIT(mb + 8, 1);
        MB_INIT(mb + 16, 1); MB_INIT(mb + 24, 1);
    }
    __syncthreads();

    // =================== phase 1: S = mask(Q @ K^T) ===================
    auto p1_load = [&](int c, int s) {
        if (t == 0) {
            const uint32_t sb = smA + s * P1_STG;
            const uint32_t m1 = mb + s * 8;
            MB_EXPECT(m1, 81920);
            BULK_G2S(sb + AT_KH, Kh + ((long)c * A_PLANE + gk * 128), 36864, m1);
            BULK_G2S(sb + AT_KL, Kl + ((long)c * A_PLANE + gk * 128), 36864, m1);
            BULK_G2S(sb + AT_QH, Qh + ((long)c * A_PLANE + gq * 128), 4096, m1);
            BULK_G2S(sb + AT_QL, Ql + ((long)c * A_PLANE + gq * 128), 4096, m1);
        }
    };

    float acc[9][4];
    #pragma unroll
    for (int n = 0; n < 9; n++)
        #pragma unroll
        for (int r = 0; r < 4; r++) acc[n][r] = 0.f;

    p1_load(0, 0);
    int pf1[2] = {0, 0};

    for (int c = 0; c < NCH; ++c) {
        const int s = c & 1;
        if (c + 1 < NCH) p1_load(c + 1, s ^ 1);
        MB_WAIT(mb + s * 8, pf1[s]);
        pf1[s] ^= 1;

        const uint32_t sb = smA + s * P1_STG;
        #pragma unroll
        for (int k16 = 0; k16 < 64; k16 += 16) {
            uint32_t ah[4], al[4];
            {
                const int row = wm * 16 + l15;
                const int u   = ((k16 >> 3) + uA) ^ (row & 7);
                const uint32_t ao = (uint32_t)(row * 128 + (u << 4));
                ldsm_x4(ah, sb + AT_QH + ao);
                ldsm_x4(al, sb + AT_QL + ao);
            }
            uint32_t bh[9][2], bl[9][2];
            #pragma unroll
            for (int p = 0; p < 4; p++) {
                const int row = wn * 72 + p * 16 + brow;
                const int u   = ((k16 >> 3) + uB) ^ (row & 7);
                const uint32_t bo = (uint32_t)(row * 128 + (u << 4));
                uint32_t r4[4];
                ldsm_x4(r4, sb + AT_KH + bo);
                bh[2*p][0] = r4[0]; bh[2*p][1] = r4[1];
                bh[2*p+1][0] = r4[2]; bh[2*p+1][1] = r4[3];
                ldsm_x4(r4, sb + AT_KL + bo);
                bl[2*p][0] = r4[0]; bl[2*p][1] = r4[1];
                bl[2*p+1][0] = r4[2]; bl[2*p+1][1] = r4[3];
            }
            {
                const int row = wn * 72 + 64 + brl;
                const int u   = ((k16 >> 3) + ((lane >> 3) & 1)) ^ (row & 7);
                const uint32_t bo = (uint32_t)(row * 128 + (u << 4));
                ldsm_x2(bh[8], sb + AT_KH + bo);
                ldsm_x2(bl[8], sb + AT_KL + bo);
            }
            #pragma unroll
            for (int nt = 0; nt < 9; nt++) {
                mma_bf16(acc[nt], ah, bh[nt]);
                mma_bf16(acc[nt], ah, bl[nt]);
                mma_bf16(acc[nt], al, bh[nt]);
            }
        }
        __syncthreads();
    }

    // mask + scale + split hi/lo into S smem
    #pragma unroll
    for (int nt = 0; nt < 9; nt++) {
        const int jw0 = wn * 72 + nt * 8 + qid * 2;
        #pragma unroll
        for (int half = 0; half < 2; half++) {
            const int ti = wm * 16 + gid + half * 8;
            float v0 = acc[nt][half * 2];
            float v1 = acc[nt][half * 2 + 1];
            const bool ok0 = (jb + jw0     >= 0) && (jw0     > ti) && (jw0     <= ti + 256);
            const bool ok1 = (jb + jw0 + 1 >= 0) && (jw0 + 1 > ti) && (jw0 + 1 <= ti + 256);
            v0 = ok0 ? v0 * INV_SCALE : 0.f;
            v1 = ok1 ? v1 * INV_SCALE : 0.f;
            uint32_t lo;
            const uint32_t hi = pack_hl(v0, v1, lo);
            const uint32_t so = (uint32_t)(ti * SSTR + jw0) * 2;
            *(uint32_t*)(smc + AT_SH + so) = hi;
            *(uint32_t*)(smc + AT_SL + so) = lo;
        }
    }
    __syncthreads();

    // =================== phase 2: Y = S @ V ===================
    auto p2_load = [&](int iter, int s) {
        if (t == 0) {
            const int dc = iter / 9;
            const int js = iter % 9;
            const long r0 = gk + js * 32;
            const uint32_t sb = smA + s * AT_P2S;
            const uint32_t m2 = mb + 16 + s * 8;
            MB_EXPECT(m2, 32768);
            #pragma unroll
            for (int q = 0; q < 4; q++) {
                const int cv = dc * 4 + q;
                BULK_G2S(sb + q * 4096,         Vh + ((long)cv * A_PLANE + r0 * 128), 4096, m2);
                BULK_G2S(sb + 16384 + q * 4096, Vl + ((long)cv * A_PLANE + r0 * 128), 4096, m2);
            }
        }
    };

    float acc2[8][4];
    #pragma unroll
    for (int n = 0; n < 8; n++)
        #pragma unroll
        for (int r = 0; r < 4; r++) acc2[n][r] = 0.f;

    p2_load(0, 0);
    p2_load(1, 1);
    int ph2[2] = {0, 0};

    for (int iter = 0; iter < 27; ++iter) {
        const int s = iter & 1;
        MB_WAIT(mb + 16 + s * 8, ph2[s]);
        ph2[s] ^= 1;

        const int js = (iter % 9) * 32;
        const uint32_t sb = smA + s * AT_P2S;
        #pragma unroll
        for (int k16 = 0; k16 < 32; k16 += 16) {
            uint32_t ah[4], al[4];
            const uint32_t ao = (uint32_t)((wm * 16 + l15) * SSTR + js + k16 + uA * 8) * 2;
            ldsm_x4(ah, smb + AT_SH + ao);
            ldsm_x4(al, smb + AT_SL + ao);

            uint32_t bh[8][2], bl[8][2];
            #pragma unroll
            for (int p = 0; p < 4; p++) {
                const int row = k16 + l15;
                const int u   = (2 * p + uA) ^ (row & 7);
                const uint32_t bo = (uint32_t)(wn * 4096 + row * 128 + (u << 4));
                uint32_t r4[4];
                ldsm_x4_t(r4, sb + bo);
                bh[2*p][0] = r4[0]; bh[2*p][1] = r4[1];
                bh[2*p+1][0] = r4[2]; bh[2*p+1][1] = r4[3];
                ldsm_x4_t(r4, sb + 16384 + bo);
                bl[2*p][0] = r4[0]; bl[2*p][1] = r4[1];
                bl[2*p+1][0] = r4[2]; bl[2*p+1][1] = r4[3];
            }
            #pragma unroll
            for (int nt = 0; nt < 8; nt++) {
                mma_bf16(acc2[nt], ah, bh[nt]);
                mma_bf16(acc2[nt], ah, bl[nt]);
                mma_bf16(acc2[nt], al, bh[nt]);
            }
        }

        if ((iter % 9) == 8) {
            const int dc = (iter / 9) * 256;
            #pragma unroll
            for (int nt = 0; nt < 8; nt++) {
                const int col = dc + wn * 64 + nt * 8 + qid * 2;
                #pragma unroll
                for (int half = 0; half < 2; half++) {
                    const long row = gq + wm * 16 + gid + half * 8;
                    *(float2*)&Y[row * DD + col] =
                        make_float2(acc2[nt][half * 2], acc2[nt][half * 2 + 1]);
                }
            }
            #pragma unroll
            for (int n = 0; n < 8; n++)
                #pragma unroll
                for (int r = 0; r < 4; r++) acc2[n][r] = 0.f;
        }
        __syncthreads();
        if (iter + 2 < 27) p2_load(iter + 2, s);
    }
}

// ---------------------------------------------------------------------------
// row LayerNorm: out = (y-mu)*rstd*w + b.  1 warp per row, 8 rows per block.
// ---------------------------------------------------------------------------
__global__ void __launch_bounds__(256) ln_kernel(
    const float* __restrict__ Y, const float* __restrict__ lnw,
    const float* __restrict__ lnb, float* __restrict__ out)
{
    const int warp = threadIdx.x >> 5;
    const int lane = threadIdx.x & 31;
    const long row = (long)blockIdx.x * 8 + warp;
    const float* y = Y + row * DD;

    float4 v[6];
    float s = 0.f, ss = 0.f;
    #pragma unroll
    for (int i = 0; i < 6; i++) {
        v[i] = *(const float4*)(y + (i * 32 + lane) * 4);
        s  += v[i].x + v[i].y + v[i].z + v[i].w;
        ss += v[i].x * v[i].x + v[i].y * v[i].y + v[i].z * v[i].z + v[i].w * v[i].w;
    }
    #pragma unroll
    for (int o = 16; o > 0; o >>= 1) {
        s  += __shfl_xor_sync(0xffffffffu, s,  o);
        ss += __shfl_xor_sync(0xffffffffu, ss, o);
    }
    const float mu   = s * (1.f / 768.f);
    const float var  = ss * (1.f / 768.f) - mu * mu;
    const float rstd = rsqrtf(var + 1e-5f);

    float* o = out + row * DD;
    #pragma unroll
    for (int i = 0; i < 6; i++) {
        const int c = (i * 32 + lane) * 4;
        const float4 w4 = *(const float4*)(lnw + c);
        const float4 b4 = *(const float4*)(lnb + c);
        float4 r;
        r.x = (v[i].x - mu) * rstd * w4.x + b4.x;
        r.y = (v[i].y - mu) * rstd * w4.y + b4.y;
        r.z = (v[i].z - mu) * rstd * w4.z + b4.z;
        r.w = (v[i].w - mu) * rstd * w4.w + b4.w;
        *(float4*)(o + c) = r;
    }
}

// ---------------------------------------------------------------------------
extern "C" void kernel_launch(void* const* d_in, const int* in_sizes, int n_in,
                              void* d_out, int out_size)
{
    const float* x   = (const float*)d_in[0];
    const float* qw1 = (const float*)d_in[1];
    const float* qb1 = (const float*)d_in[2];
    const float* qw2 = (const float*)d_in[3];
    const float* qb2 = (const float*)d_in[4];
    const float* kw1 = (const float*)d_in[5];
    const float* kb1 = (const float*)d_in[6];
    const float* kw2 = (const float*)d_in[7];
    const float* kb2 = (const float*)d_in[8];
    const float* vw1 = (const float*)d_in[9];
    const float* vb1 = (const float*)d_in[10];
    const float* vw2 = (const float*)d_in[11];
    const float* vb2 = (const float*)d_in[12];
    const float* lnw = (const float*)d_in[13];
    const float* lnb = (const float*)d_in[14];
    float* out = (float*)d_out;

    uint8_t *Xh, *Xl, *Hh, *Hl, *W1h, *W1l, *W2h, *W2l, *QKVh, *QKVl;
    float* Y;
    cudaGetSymbolAddress((void**)&Xh, g_Xh);
    cudaGetSymbolAddress((void**)&Xl, g_Xl);
    cudaGetSymbolAddress((void**)&Hh, g_Hh);
    cudaGetSymbolAddress((void**)&Hl, g_Hl);
    cudaGetSymbolAddress((void**)&W1h, g_W1h);
    cudaGetSymbolAddress((void**)&W1l, g_W1l);
    cudaGetSymbolAddress((void**)&W2h, g_W2h);
    cudaGetSymbolAddress((void**)&W2l, g_W2l);
    cudaGetSymbolAddress((void**)&QKVh, g_QKVh);
    cudaGetSymbolAddress((void**)&QKVl, g_QKVl);
    cudaGetSymbolAddress((void**)&Y, g_Y);

    cudaFuncSetAttribute(mma_gemm_kernel<1>,
                         cudaFuncAttributeMaxDynamicSharedMemorySize, GEMM_SMEM);
    cudaFuncSetAttribute(mma_gemm_kernel<2>,
                         cudaFuncAttributeMaxDynamicSharedMemorySize, GEMM_SMEM);
    cudaFuncSetAttribute(attn_kernel,
                         cudaFuncAttributeMaxDynamicSharedMemorySize, ATTN_SMEM);

    convert_x_kernel<<<(MT * DD) / (256 * 8), 256>>>(x, Xh, Xl);

    const dim3 gw(24, 24);
    const dim3 bw(32, 8);
    const float* W1[3] = {qw1, kw1, vw1};
    const float* W2[3] = {qw2, kw2, vw2};
    for (int m = 0; m < 3; m++) {
        convert_wt_kernel<<<gw, bw>>>(W1[m], W1h + (size_t)m * SZ_W, W1l + (size_t)m * SZ_W);
        convert_wt_kernel<<<gw, bw>>>(W2[m], W2h + (size_t)m * SZ_W, W2l + (size_t)m * SZ_W);
    }

    const dim3 gg(DD / 128, MT / 256, 3);
    mma_gemm_kernel<1><<<gg, 512, GEMM_SMEM>>>(Xh, Xl, W1h, W1l,
                                               qb1, kb1, vb1, Hh, Hl);
    mma_gemm_kernel<2><<<gg, 512, GEMM_SMEM>>>(Hh, Hl, W2h, W2l,
                                               qb2, kb2, vb2, QKVh, QKVl);

    attn_kernel<<<MT / TQ, 256, ATTN_SMEM>>>(
        QKVh + PAD_B,               QKVl + PAD_B,
        QKVh + SLOT + PAD_B,        QKVl + SLOT + PAD_B,
        QKVh + 2ull * SLOT + PAD_B, QKVl + 2ull * SLOT + PAD_B,
        Y);

    ln_kernel<<<MT / 8, 256>>>(Y, lnw, lnb, out);
}

// round 9
// speedup vs baseline: 2.0414x; 1.3555x over previous
#include <cuda_runtime.h>
#include <cuda_fp16.h>
#include <math.h>
#include <stdint.h>

#define MT 16384
#define DD 768
#define NCH 12                       // K chunks of 64
#define A_PLANE (MT * 128)           // bytes per chunk plane (M=16384)
#define W_PLANE (DD * 128)           // bytes per chunk plane (M=768)
#define SZ_X ((size_t)MT * DD * 2)
#define SZ_W ((size_t)DD * DD * 2)
#define PAD_B 32768                  // 256 rows x 128B zero pad before QKV planes
#define SLOT (PAD_B + SZ_X)

// GEMM smem stage: Ah 32K | Al 32K | B 16K
#define STG_AL 32768
#define STG_B  65536
#define STAGE  81920
#define GEMM_SMEM (2 * STAGE)

// ---- attention ----
#define TQ 32
#define SSTR 296
#define AT_SH 0
#define AT_SL 18944
#define AT_A  37888
#define P1_STG 45056                 // per stage: KH 36864 | QH 4096 | QL 4096
#define AT_QH 36864
#define AT_QL 40960
#define AT_P2S 16384                 // per-stage: VH only
#define ATTN_SMEM 128000             // AT_A + 2*P1_STG

#define INV_SCALE 0.0022552744890219756f

// ---------------------------------------------------------------------------
__device__ __align__(128) uint8_t g_Xh[SZ_X];
__device__ __align__(128) uint8_t g_Xl[SZ_X];
__device__ __align__(128) uint8_t g_Hh[3 * SZ_X];
__device__ __align__(128) uint8_t g_Hl[3 * SZ_X];
__device__ __align__(128) uint8_t g_W1[3 * SZ_W];
__device__ __align__(128) uint8_t g_W2[3 * SZ_W];
__device__ __align__(128) uint8_t g_QKVh[3 * SLOT];   // zero-init pads
__device__ __align__(128) uint8_t g_QKVl[3 * SLOT];
__device__ float g_Y[(size_t)MT * DD];

__device__ __forceinline__ float gelu_exact(float x) {
    return 0.5f * x * (1.0f + erff(x * 0.70710678118654752f));
}
__device__ __forceinline__ uint32_t s2u(const void* p) {
    uint32_t a;
    asm("{ .reg .u64 t; cvta.to.shared.u64 t, %1; cvt.u32.u64 %0, t; }"
        : "=r"(a) : "l"(p));
    return a;
}
__device__ __forceinline__ size_t toff(int row, int k, size_t plane) {
    const int u = ((k >> 3) & 7) ^ (row & 7);
    return (size_t)(k >> 6) * plane + (size_t)row * 128 + (size_t)(u << 4) + (size_t)(k & 7) * 2;
}

// ---- primitives ----
__device__ __forceinline__ void mma_f16(float* c, const uint32_t* a, const uint32_t* b) {
    asm volatile(
        "mma.sync.aligned.m16n8k16.row.col.f32.f16.f16.f32 "
        "{%0,%1,%2,%3}, {%4,%5,%6,%7}, {%8,%9}, {%0,%1,%2,%3};"
        : "+f"(c[0]), "+f"(c[1]), "+f"(c[2]), "+f"(c[3])
        : "r"(a[0]), "r"(a[1]), "r"(a[2]), "r"(a[3]), "r"(b[0]), "r"(b[1]));
}
__device__ __forceinline__ void ldsm_x4(uint32_t* r, uint32_t addr) {
    asm volatile("ldmatrix.sync.aligned.m8n8.x4.shared.b16 {%0,%1,%2,%3}, [%4];"
                 : "=r"(r[0]), "=r"(r[1]), "=r"(r[2]), "=r"(r[3]) : "r"(addr));
}
__device__ __forceinline__ void ldsm_x4_t(uint32_t* r, uint32_t addr) {
    asm volatile("ldmatrix.sync.aligned.m8n8.x4.trans.shared.b16 {%0,%1,%2,%3}, [%4];"
                 : "=r"(r[0]), "=r"(r[1]), "=r"(r[2]), "=r"(r[3]) : "r"(addr));
}
__device__ __forceinline__ void ldsm_x2(uint32_t* r, uint32_t addr) {
    asm volatile("ldmatrix.sync.aligned.m8n8.x2.shared.b16 {%0,%1}, [%2];"
                 : "=r"(r[0]), "=r"(r[1]) : "r"(addr));
}
#define MB_INIT(addr, cnt) \
    asm volatile("mbarrier.init.shared.b64 [%0], %1;" :: "r"(addr), "r"(cnt) : "memory")
#define MB_EXPECT(addr, tx) \
    asm volatile("mbarrier.arrive.expect_tx.shared.b64 _, [%0], %1;" :: "r"(addr), "r"(tx) : "memory")
#define MB_ARRIVE(addr) \
    asm volatile("mbarrier.arrive.shared.b64 _, [%0];" :: "r"(addr) : "memory")
#define BULK_G2S(dst, src, sz, mb) \
    asm volatile("cp.async.bulk.shared::cluster.global.mbarrier::complete_tx::bytes [%0], [%1], %2, [%3];" \
                 :: "r"(dst), "l"(src), "r"(sz), "r"(mb) : "memory")
#define MB_WAIT(addr, par) do {                                                \
    uint32_t _m = (addr), _p = (par), _d;                                      \
    asm volatile("{\n\t.reg .pred p;\n\t"                                      \
        "mbarrier.try_wait.parity.acquire.cta.shared::cta.b64 p, [%1], %2;\n\t"\
        "selp.b32 %0, 1, 0, p;\n\t}"                                           \
        : "=r"(_d) : "r"(_m), "r"(_p) : "memory");                             \
    if (!_d) {                                                                 \
        asm volatile("{\n\t.reg .pred P1;\n\t"                                 \
            "WL_%=:\n\t"                                                       \
            "mbarrier.try_wait.parity.acquire.cta.shared::cta.b64 P1, [%0], %1, 0x989680;\n\t" \
            "@P1 bra.uni WD_%=;\n\t"                                           \
            "bra.uni WL_%=;\n\t"                                               \
            "WD_%=:\n\t}"                                                      \
            :: "r"(_m), "r"(_p) : "memory");                                   \
    }                                                                          \
} while (0)

__device__ __forceinline__ uint32_t pack_hl_f16(float v, float w, uint32_t& lo) {
    __half h0 = __float2half_rn(v);
    __half h1 = __float2half_rn(w);
    __half l0 = __float2half_rn(v - __half2float(h0));
    __half l1 = __float2half_rn(w - __half2float(h1));
    lo = (uint32_t)__half_as_ushort(l0) | ((uint32_t)__half_as_ushort(l1) << 16);
    return (uint32_t)__half_as_ushort(h0) | ((uint32_t)__half_as_ushort(h1) << 16);
}

// ---------------------------------------------------------------------------
__global__ void convert_x_kernel(const float* __restrict__ X,
                                 uint8_t* __restrict__ Xh,
                                 uint8_t* __restrict__ Xl) {
    const long gi = (long)(blockIdx.x * blockDim.x + threadIdx.x) * 8;
    const int row = (int)(gi / DD);
    const int k   = (int)(gi % DD);
    const float4 v0 = *(const float4*)(X + gi);
    const float4 v1 = *(const float4*)(X + gi + 4);
    uint32_t h[4], l[4];
    h[0] = pack_hl_f16(v0.x, v0.y, l[0]);
    h[1] = pack_hl_f16(v0.z, v0.w, l[1]);
    h[2] = pack_hl_f16(v1.x, v1.y, l[2]);
    h[3] = pack_hl_f16(v1.z, v1.w, l[3]);
    const size_t o = toff(row, k, A_PLANE);
    *(uint4*)(Xh + o) = make_uint4(h[0], h[1], h[2], h[3]);
    *(uint4*)(Xl + o) = make_uint4(l[0], l[1], l[2], l[3]);
}

__global__ void convert_wt_kernel(const float* __restrict__ W,
                                  uint8_t* __restrict__ Wt) {
    __shared__ float tile[32][33];
    const int bx = blockIdx.x * 32;
    const int by = blockIdx.y * 32;
    const int tx = threadIdx.x, ty = threadIdx.y;
    for (int r = ty; r < 32; r += 8)
        tile[r][tx] = W[(size_t)(by + r) * DD + bx + tx];
    __syncthreads();
    for (int r = ty; r < 32; r += 8) {
        const float v = tile[tx][r];
        const size_t o = toff(bx + r, by + tx, W_PLANE);
        *(__half*)(Wt + o) = __float2half_rn(v);
    }
}

// ---------------------------------------------------------------------------
// fp16x2 GEMM (A split hi/lo, B single); producer/consumer mbarrier mainloop.
// ---------------------------------------------------------------------------
template<int LAYER>
__global__ void __launch_bounds__(512) mma_gemm_kernel(
    const uint8_t* __restrict__ Abh, const uint8_t* __restrict__ Abl,
    const uint8_t* __restrict__ Bb,
    const float* __restrict__ bias0, const float* __restrict__ bias1,
    const float* __restrict__ bias2,
    uint8_t* __restrict__ Ch, uint8_t* __restrict__ Cl)
{
    extern __shared__ char sm[];
    __shared__ uint64_t s_mbar[4];   // full0, full1, empty0, empty1
    const uint32_t smb = s2u(sm);
    const uint32_t mb0 = s2u(&s_mbar[0]);

    const int t    = threadIdx.x;
    const int warp = t >> 5;
    const int lane = t & 31;
    const int wm   = warp & 7;
    const int wn   = warp >> 3;
    const int n0   = blockIdx.x * 128;
    const int m0   = blockIdx.y * 256;
    const int z    = blockIdx.z;

    const uint8_t* Ah = Abh + (LAYER == 2 ? (size_t)z * SZ_X : 0);
    const uint8_t* Al = Abl + (LAYER == 2 ? (size_t)z * SZ_X : 0);
    const uint8_t* Bp = Bb + (size_t)z * SZ_W;
    const float* bias = (z == 0) ? bias0 : (z == 1) ? bias1 : bias2;

    if (t == 0) {
        MB_INIT(mb0, 1);  MB_INIT(mb0 + 8, 1);
        MB_INIT(mb0 + 16, 16);  MB_INIT(mb0 + 24, 16);
    }
    __syncthreads();

    auto load_chunk = [&](int c, int s) {
        const uint32_t sb = smb + s * STAGE;
        const uint32_t mb = mb0 + s * 8;
        MB_EXPECT(mb, STAGE);
        BULK_G2S(sb,          Ah + (size_t)c * A_PLANE + (size_t)m0 * 128, 32768, mb);
        BULK_G2S(sb + STG_AL, Al + (size_t)c * A_PLANE + (size_t)m0 * 128, 32768, mb);
        BULK_G2S(sb + STG_B,  Bp + (size_t)c * W_PLANE + (size_t)n0 * 128, 16384, mb);
    };

    const int l15   = lane & 15;
    const int uA    = lane >> 4;
    const int q3    = lane >> 3;
    const int brl   = lane & 7;
    const int brow  = (q3 < 2) ? brl : (8 + brl);
    const int uB    = q3 & 1;

    float acc[2][8][4];
    #pragma unroll
    for (int i = 0; i < 2; i++)
        #pragma unroll
        for (int j = 0; j < 8; j++)
            #pragma unroll
            for (int r = 0; r < 4; r++) acc[i][j][r] = 0.f;

    if (t == 0) load_chunk(0, 0);
    int pf[2] = {0, 0}, pe[2] = {0, 0};

    for (int c = 0; c < NCH; ++c) {
        const int s = c & 1;
        if (c + 1 < NCH && t == 0) {
            if (c >= 1) { MB_WAIT(mb0 + 16 + (s ^ 1) * 8, pe[s ^ 1]); pe[s ^ 1] ^= 1; }
            load_chunk(c + 1, s ^ 1);
        }
        MB_WAIT(mb0 + s * 8, pf[s]);
        pf[s] ^= 1;

        const uint32_t sb = smb + s * STAGE;
        #pragma unroll
        for (int k16 = 0; k16 < 64; k16 += 16) {
            uint32_t ah[2][4], al[2][4];
            #pragma unroll
            for (int mt = 0; mt < 2; mt++) {
                const int row = wm * 32 + mt * 16 + l15;
                const int u   = ((k16 >> 3) + uA) ^ (row & 7);
                const uint32_t ao = (uint32_t)(row * 128 + (u << 4));
                ldsm_x4(ah[mt], sb + ao);
                ldsm_x4(al[mt], sb + STG_AL + ao);
            }
            #pragma unroll
            for (int p = 0; p < 4; p++) {
                const int row = wn * 64 + p * 16 + brow;
                const int u   = ((k16 >> 3) + uB) ^ (row & 7);
                const uint32_t bo = (uint32_t)(row * 128 + (u << 4));
                uint32_t rh[4];
                ldsm_x4(rh, sb + STG_B + bo);
                #pragma unroll
                for (int h = 0; h < 2; h++) {
                    const int nt = 2 * p + h;
                    #pragma unroll
                    for (int mt = 0; mt < 2; mt++) {
                        mma_f16(acc[mt][nt], ah[mt], rh + 2 * h);
                        mma_f16(acc[mt][nt], al[mt], rh + 2 * h);
                    }
                }
            }
        }
        if (lane == 0) MB_ARRIVE(mb0 + 16 + s * 8);
    }

    const int gid = lane >> 2;
    const int qid = lane & 3;
    #pragma unroll
    for (int mt = 0; mt < 2; mt++) {
        #pragma unroll
        for (int nt = 0; nt < 8; nt++) {
            const int col = n0 + wn * 64 + nt * 8 + qid * 2;
            const float b0 = bias[col], b1 = bias[col + 1];
            #pragma unroll
            for (int half = 0; half < 2; half++) {
                const int row = m0 + wm * 32 + mt * 16 + gid + half * 8;
                float v0 = acc[mt][nt][half * 2]     + b0;
                float v1 = acc[mt][nt][half * 2 + 1] + b1;
                if (LAYER == 1) { v0 = gelu_exact(v0); v1 = gelu_exact(v1); }
                uint32_t lo;
                const uint32_t hi = pack_hl_f16(v0, v1, lo);
                if (LAYER == 1) {
                    const size_t o = (size_t)z * SZ_X + toff(row, col, A_PLANE);
                    *(uint32_t*)(Ch + o) = hi;
                    *(uint32_t*)(Cl + o) = lo;
                } else {
                    const size_t o = (size_t)z * SLOT + PAD_B + toff(row, col, A_PLANE);
                    *(uint32_t*)(Ch + o) = hi;
                    if (z == 0) *(uint32_t*)(Cl + o) = lo;   // only Q needs lo
                }
            }
        }
    }
}

// ---------------------------------------------------------------------------
// Banded attention: S = mask(Q@K^T) (Q split, K single), Y = S@V (S split,
// V single). Y -> gmem fp32; LN separate. Phase 1 double-buffered.
// ---------------------------------------------------------------------------
__global__ void __launch_bounds__(256) attn_kernel(
    const uint8_t* __restrict__ Qh, const uint8_t* __restrict__ Ql,
    const uint8_t* __restrict__ Kh, const uint8_t* __restrict__ Vh,
    float* __restrict__ Y)
{
    extern __shared__ char smc[];
    __shared__ uint64_t s_mb[4];     // p1f0, p1f1, p2f0, p2f1
    const uint32_t smb = s2u(smc);
    const uint32_t smA = smb + AT_A;
    const uint32_t mb = s2u(&s_mb[0]);

    const int t    = threadIdx.x;
    const int warp = t >> 5;
    const int lane = t & 31;
    const int wm   = warp >> 2;
    const int wn   = warp & 3;
    const int gid  = lane >> 2;
    const int qid  = lane & 3;

    const int bx = blockIdx.x;
    const int b  = bx >> 7;
    const int i0 = (bx & 127) * TQ;
    const long base = (long)b * 4096;
    const long gq   = base + i0;
    const long gk   = base + i0 - 256;
    const int jb = i0 - 256;

    const int l15  = lane & 15;
    const int uA   = lane >> 4;
    const int q3   = lane >> 3;
    const int brl  = lane & 7;
    const int brow = (q3 < 2) ? brl : (8 + brl);
    const int uB   = q3 & 1;

    if (t == 0) {
        MB_INIT(mb, 1); MB_INIT(mb + 8, 1);
        MB_INIT(mb + 16, 1); MB_INIT(mb + 24, 1);
    }
    __syncthreads();

    // =================== phase 1: S = mask(Q @ K^T) ===================
    auto p1_load = [&](int c, int s) {
        if (t == 0) {
            const uint32_t sb = smA + s * P1_STG;
            const uint32_t m1 = mb + s * 8;
            MB_EXPECT(m1, 45056);
            BULK_G2S(sb,         Kh + ((long)c * A_PLANE + gk * 128), 36864, m1);
            BULK_G2S(sb + AT_QH, Qh + ((long)c * A_PLANE + gq * 128), 4096, m1);
            BULK_G2S(sb + AT_QL, Ql + ((long)c * A_PLANE + gq * 128), 4096, m1);
        }
    };

    float acc[9][4];
    #pragma unroll
    for (int n = 0; n < 9; n++)
        #pragma unroll
        for (int r = 0; r < 4; r++) acc[n][r] = 0.f;

    p1_load(0, 0);
    int pf1[2] = {0, 0};

    for (int c = 0; c < NCH; ++c) {
        const int s = c & 1;
        if (c + 1 < NCH) p1_load(c + 1, s ^ 1);
        MB_WAIT(mb + s * 8, pf1[s]);
        pf1[s] ^= 1;

        const uint32_t sb = smA + s * P1_STG;
        #pragma unroll
        for (int k16 = 0; k16 < 64; k16 += 16) {
            uint32_t ah[4], al[4];
            {
                const int row = wm * 16 + l15;
                const int u   = ((k16 >> 3) + uA) ^ (row & 7);
                const uint32_t ao = (uint32_t)(row * 128 + (u << 4));
                ldsm_x4(ah, sb + AT_QH + ao);
                ldsm_x4(al, sb + AT_QL + ao);
            }
            uint32_t bh[9][2];
            #pragma unroll
            for (int p = 0; p < 4; p++) {
                const int row = wn * 72 + p * 16 + brow;
                const int u   = ((k16 >> 3) + uB) ^ (row & 7);
                const uint32_t bo = (uint32_t)(row * 128 + (u << 4));
                uint32_t r4[4];
                ldsm_x4(r4, sb + bo);
                bh[2*p][0] = r4[0]; bh[2*p][1] = r4[1];
                bh[2*p+1][0] = r4[2]; bh[2*p+1][1] = r4[3];
            }
            {
                const int row = wn * 72 + 64 + brl;
                const int u   = ((k16 >> 3) + ((lane >> 3) & 1)) ^ (row & 7);
                const uint32_t bo = (uint32_t)(row * 128 + (u << 4));
                ldsm_x2(bh[8], sb + bo);
            }
            #pragma unroll
            for (int nt = 0; nt < 9; nt++) {
                mma_f16(acc[nt], ah, bh[nt]);
                mma_f16(acc[nt], al, bh[nt]);
            }
        }
        __syncthreads();
    }

    // mask + scale + split hi/lo into S smem
    #pragma unroll
    for (int nt = 0; nt < 9; nt++) {
        const int jw0 = wn * 72 + nt * 8 + qid * 2;
        #pragma unroll
        for (int half = 0; half < 2; half++) {
            const int ti = wm * 16 + gid + half * 8;
            float v0 = acc[nt][half * 2];
            float v1 = acc[nt][half * 2 + 1];
            const bool ok0 = (jb + jw0     >= 0) && (jw0     > ti) && (jw0     <= ti + 256);
            const bool ok1 = (jb + jw0 + 1 >= 0) && (jw0 + 1 > ti) && (jw0 + 1 <= ti + 256);
            v0 = ok0 ? v0 * INV_SCALE : 0.f;
            v1 = ok1 ? v1 * INV_SCALE : 0.f;
            uint32_t lo;
            const uint32_t hi = pack_hl_f16(v0, v1, lo);
            const uint32_t so = (uint32_t)(ti * SSTR + jw0) * 2;
            *(uint32_t*)(smc + AT_SH + so) = hi;
            *(uint32_t*)(smc + AT_SL + so) = lo;
        }
    }
    __syncthreads();

    // =================== phase 2: Y = S @ V ===================
    auto p2_load = [&](int iter, int s) {
        if (t == 0) {
            const int dc = iter / 9;
            const int js = iter % 9;
            const long r0 = gk + js * 32;
            const uint32_t sb = smA + s * AT_P2S;
            const uint32_t m2 = mb + 16 + s * 8;
            MB_EXPECT(m2, 16384);
            #pragma unroll
            for (int q = 0; q < 4; q++) {
                const int cv = dc * 4 + q;
                BULK_G2S(sb + q * 4096, Vh + ((long)cv * A_PLANE + r0 * 128), 4096, m2);
            }
        }
    };

    float acc2[8][4];
    #pragma unroll
    for (int n = 0; n < 8; n++)
        #pragma unroll
        for (int r = 0; r < 4; r++) acc2[n][r] = 0.f;

    p2_load(0, 0);
    p2_load(1, 1);
    int ph2[2] = {0, 0};

    for (int iter = 0; iter < 27; ++iter) {
        const int s = iter & 1;
        MB_WAIT(mb + 16 + s * 8, ph2[s]);
        ph2[s] ^= 1;

        const int js = (iter % 9) * 32;
        const uint32_t sb = smA + s * AT_P2S;
        #pragma unroll
        for (int k16 = 0; k16 < 32; k16 += 16) {
            uint32_t ah[4], al[4];
            const uint32_t ao = (uint32_t)((wm * 16 + l15) * SSTR + js + k16 + uA * 8) * 2;
            ldsm_x4(ah, smb + AT_SH + ao);
            ldsm_x4(al, smb + AT_SL + ao);

            uint32_t bh[8][2];
            #pragma unroll
            for (int p = 0; p < 4; p++) {
                const int row = k16 + l15;
                const int u   = (2 * p + uA) ^ (row & 7);
                const uint32_t bo = (uint32_t)(wn * 4096 + row * 128 + (u << 4));
                uint32_t r4[4];
                ldsm_x4_t(r4, sb + bo);
                bh[2*p][0] = r4[0]; bh[2*p][1] = r4[1];
                bh[2*p+1][0] = r4[2]; bh[2*p+1][1] = r4[3];
            }
            #pragma unroll
            for (int nt = 0; nt < 8; nt++) {
                mma_f16(acc2[nt], ah, bh[nt]);
                mma_f16(acc2[nt], al, bh[nt]);
            }
        }

        if ((iter % 9) == 8) {
            const int dc = (iter / 9) * 256;
            #pragma unroll
            for (int nt = 0; nt < 8; nt++) {
                const int col = dc + wn * 64 + nt * 8 + qid * 2;
                #pragma unroll
                for (int half = 0; half < 2; half++) {
                    const long row = gq + wm * 16 + gid + half * 8;
                    *(float2*)&Y[row * DD + col] =
                        make_float2(acc2[nt][half * 2], acc2[nt][half * 2 + 1]);
                }
            }
            #pragma unroll
            for (int n = 0; n < 8; n++)
                #pragma unroll
                for (int r = 0; r < 4; r++) acc2[n][r] = 0.f;
        }
        __syncthreads();
        if (iter + 2 < 27) p2_load(iter + 2, s);
    }
}

// ---------------------------------------------------------------------------
__global__ void __launch_bounds__(256) ln_kernel(
    const float* __restrict__ Y, const float* __restrict__ lnw,
    const float* __restrict__ lnb, float* __restrict__ out)
{
    const int warp = threadIdx.x >> 5;
    const int lane = threadIdx.x & 31;
    const long row = (long)blockIdx.x * 8 + warp;
    const float* y = Y + row * DD;

    float4 v[6];
    float s = 0.f, ss = 0.f;
    #pragma unroll
    for (int i = 0; i < 6; i++) {
        v[i] = *(const float4*)(y + (i * 32 + lane) * 4);
        s  += v[i].x + v[i].y + v[i].z + v[i].w;
        ss += v[i].x * v[i].x + v[i].y * v[i].y + v[i].z * v[i].z + v[i].w * v[i].w;
    }
    #pragma unroll
    for (int o = 16; o > 0; o >>= 1) {
        s  += __shfl_xor_sync(0xffffffffu, s,  o);
        ss += __shfl_xor_sync(0xffffffffu, ss, o);
    }
    const float mu   = s * (1.f / 768.f);
    const float var  = ss * (1.f / 768.f) - mu * mu;
    const float rstd = rsqrtf(var + 1e-5f);

    float* o = out + row * DD;
    #pragma unroll
    for (int i = 0; i < 6; i++) {
        const int c = (i * 32 + lane) * 4;
        const float4 w4 = *(const float4*)(lnw + c);
        const float4 b4 = *(const float4*)(lnb + c);
        float4 r;
        r.x = (v[i].x - mu) * rstd * w4.x + b4.x;
        r.y = (v[i].y - mu) * rstd * w4.y + b4.y;
        r.z = (v[i].z - mu) * rstd * w4.z + b4.z;
        r.w = (v[i].w - mu) * rstd * w4.w + b4.w;
        *(float4*)(o + c) = r;
    }
}

// ---------------------------------------------------------------------------
extern "C" void kernel_launch(void* const* d_in, const int* in_sizes, int n_in,
                              void* d_out, int out_size)
{
    const float* x   = (const float*)d_in[0];
    const float* qw1 = (const float*)d_in[1];
    const float* qb1 = (const float*)d_in[2];
    const float* qw2 = (const float*)d_in[3];
    const float* qb2 = (const float*)d_in[4];
    const float* kw1 = (const float*)d_in[5];
    const float* kb1 = (const float*)d_in[6];
    const float* kw2 = (const float*)d_in[7];
    const float* kb2 = (const float*)d_in[8];
    const float* vw1 = (const float*)d_in[9];
    const float* vb1 = (const float*)d_in[10];
    const float* vw2 = (const float*)d_in[11];
    const float* vb2 = (const float*)d_in[12];
    const float* lnw = (const float*)d_in[13];
    const float* lnb = (const float*)d_in[14];
    float* out = (float*)d_out;

    uint8_t *Xh, *Xl, *Hh, *Hl, *W1, *W2, *QKVh, *QKVl;
    float* Y;
    cudaGetSymbolAddress((void**)&Xh, g_Xh);
    cudaGetSymbolAddress((void**)&Xl, g_Xl);
    cudaGetSymbolAddress((void**)&Hh, g_Hh);
    cudaGetSymbolAddress((void**)&Hl, g_Hl);
    cudaGetSymbolAddress((void**)&W1, g_W1);
    cudaGetSymbolAddress((void**)&W2, g_W2);
    cudaGetSymbolAddress((void**)&QKVh, g_QKVh);
    cudaGetSymbolAddress((void**)&QKVl, g_QKVl);
    cudaGetSymbolAddress((void**)&Y, g_Y);

    cudaFuncSetAttribute(mma_gemm_kernel<1>,
                         cudaFuncAttributeMaxDynamicSharedMemorySize, GEMM_SMEM);
    cudaFuncSetAttribute(mma_gemm_kernel<2>,
                         cudaFuncAttributeMaxDynamicSharedMemorySize, GEMM_SMEM);
    cudaFuncSetAttribute(attn_kernel,
                         cudaFuncAttributeMaxDynamicSharedMemorySize, ATTN_SMEM);

    convert_x_kernel<<<(MT * DD) / (256 * 8), 256>>>(x, Xh, Xl);

    const dim3 gw(24, 24);
    const dim3 bw(32, 8);
    const float* W1s[3] = {qw1, kw1, vw1};
    const float* W2s[3] = {qw2, kw2, vw2};
    for (int m = 0; m < 3; m++) {
        convert_wt_kernel<<<gw, bw>>>(W1s[m], W1 + (size_t)m * SZ_W);
        convert_wt_kernel<<<gw, bw>>>(W2s[m], W2 + (size_t)m * SZ_W);
    }

    const dim3 gg(DD / 128, MT / 256, 3);
    mma_gemm_kernel<1><<<gg, 512, GEMM_SMEM>>>(Xh, Xl, W1,
                                               qb1, kb1, vb1, Hh, Hl);
    mma_gemm_kernel<2><<<gg, 512, GEMM_SMEM>>>(Hh, Hl, W2,
                                               qb2, kb2, vb2, QKVh, QKVl);

    attn_kernel<<<MT / TQ, 256, ATTN_SMEM>>>(
        QKVh + PAD_B,               QKVl + PAD_B,
        QKVh + SLOT + PAD_B,
        QKVh + 2ull * SLOT + PAD_B,
        Y);

    ln_kernel<<<MT / 8, 256>>>(Y, lnw, lnb, out);
}

// round 10
// speedup vs baseline: 2.1136x; 1.0354x over previous
#include <cuda_runtime.h>
#include <cuda_fp16.h>
#include <math.h>
#include <stdint.h>

#define MT 16384
#define DD 768
#define NCH 12                       // K chunks of 64
#define A_PLANE (MT * 128)           // bytes per chunk plane (M=16384)
#define W_PLANE (DD * 128)           // bytes per chunk plane (M=768)
#define SZ_X ((size_t)MT * DD * 2)
#define SZ_W ((size_t)DD * DD * 2)
#define PAD_B 32768                  // 256 rows x 128B zero pad before QKV planes
#define SLOT (PAD_B + SZ_X)

// GEMM smem stage: Ah 32K | Al 32K | B 16K
#define STG_AL 32768
#define STG_B  65536
#define STAGE  81920
#define GEMM_SMEM (2 * STAGE)

// ---- attention ----
#define TQ 32
#define SSTR 296
#define AT_SH 0
#define AT_SL 18944
#define AT_A  37888
#define P1_STG 45056                 // per stage: KH 36864 | QH 4096 | QL 4096
#define AT_QH 36864
#define AT_QL 40960
#define AT_P2S 16384                 // per-stage: VH only
#define AT_Y  70656                  // AT_A + 2*AT_P2S; overlaps dead p1 stages
#define ATTN_SMEM 168960             // AT_Y + 32*768*4

#define INV_SCALE 0.0022552744890219756f

// ---------------------------------------------------------------------------
__device__ __align__(128) uint8_t g_Xh[SZ_X];
__device__ __align__(128) uint8_t g_Xl[SZ_X];
__device__ __align__(128) uint8_t g_Hh[3 * SZ_X];
__device__ __align__(128) uint8_t g_Hl[3 * SZ_X];
__device__ __align__(128) uint8_t g_W1[3 * SZ_W];
__device__ __align__(128) uint8_t g_W2[3 * SZ_W];
__device__ __align__(128) uint8_t g_QKVh[3 * SLOT];   // zero-init pads
__device__ __align__(128) uint8_t g_QKVl[3 * SLOT];

__device__ __forceinline__ float gelu_exact(float x) {
    return 0.5f * x * (1.0f + erff(x * 0.70710678118654752f));
}
__device__ __forceinline__ uint32_t s2u(const void* p) {
    uint32_t a;
    asm("{ .reg .u64 t; cvta.to.shared.u64 t, %1; cvt.u32.u64 %0, t; }"
        : "=r"(a) : "l"(p));
    return a;
}
__device__ __forceinline__ size_t toff(int row, int k, size_t plane) {
    const int u = ((k >> 3) & 7) ^ (row & 7);
    return (size_t)(k >> 6) * plane + (size_t)row * 128 + (size_t)(u << 4) + (size_t)(k & 7) * 2;
}

// ---- primitives ----
__device__ __forceinline__ void mma_f16(float* c, const uint32_t* a, const uint32_t* b) {
    asm volatile(
        "mma.sync.aligned.m16n8k16.row.col.f32.f16.f16.f32 "
        "{%0,%1,%2,%3}, {%4,%5,%6,%7}, {%8,%9}, {%0,%1,%2,%3};"
        : "+f"(c[0]), "+f"(c[1]), "+f"(c[2]), "+f"(c[3])
        : "r"(a[0]), "r"(a[1]), "r"(a[2]), "r"(a[3]), "r"(b[0]), "r"(b[1]));
}
__device__ __forceinline__ void ldsm_x4(uint32_t* r, uint32_t addr) {
    asm volatile("ldmatrix.sync.aligned.m8n8.x4.shared.b16 {%0,%1,%2,%3}, [%4];"
                 : "=r"(r[0]), "=r"(r[1]), "=r"(r[2]), "=r"(r[3]) : "r"(addr));
}
__device__ __forceinline__ void ldsm_x4_t(uint32_t* r, uint32_t addr) {
    asm volatile("ldmatrix.sync.aligned.m8n8.x4.trans.shared.b16 {%0,%1,%2,%3}, [%4];"
                 : "=r"(r[0]), "=r"(r[1]), "=r"(r[2]), "=r"(r[3]) : "r"(addr));
}
__device__ __forceinline__ void ldsm_x2(uint32_t* r, uint32_t addr) {
    asm volatile("ldmatrix.sync.aligned.m8n8.x2.shared.b16 {%0,%1}, [%2];"
                 : "=r"(r[0]), "=r"(r[1]) : "r"(addr));
}
#define MB_INIT(addr, cnt) \
    asm volatile("mbarrier.init.shared.b64 [%0], %1;" :: "r"(addr), "r"(cnt) : "memory")
#define MB_EXPECT(addr, tx) \
    asm volatile("mbarrier.arrive.expect_tx.shared.b64 _, [%0], %1;" :: "r"(addr), "r"(tx) : "memory")
#define MB_ARRIVE(addr) \
    asm volatile("mbarrier.arrive.shared.b64 _, [%0];" :: "r"(addr) : "memory")
#define BULK_G2S(dst, src, sz, mb) \
    asm volatile("cp.async.bulk.shared::cluster.global.mbarrier::complete_tx::bytes [%0], [%1], %2, [%3];" \
                 :: "r"(dst), "l"(src), "r"(sz), "r"(mb) : "memory")
#define MB_WAIT(addr, par) do {                                                \
    uint32_t _m = (addr), _p = (par), _d;                                      \
    asm volatile("{\n\t.reg .pred p;\n\t"                                      \
        "mbarrier.try_wait.parity.acquire.cta.shared::cta.b64 p, [%1], %2;\n\t"\
        "selp.b32 %0, 1, 0, p;\n\t}"                                           \
        : "=r"(_d) : "r"(_m), "r"(_p) : "memory");                             \
    if (!_d) {                                                                 \
        asm volatile("{\n\t.reg .pred P1;\n\t"                                 \
            "WL_%=:\n\t"                                                       \
            "mbarrier.try_wait.parity.acquire.cta.shared::cta.b64 P1, [%0], %1, 0x989680;\n\t" \
            "@P1 bra.uni WD_%=;\n\t"                                           \
            "bra.uni WL_%=;\n\t"                                               \
            "WD_%=:\n\t}"                                                      \
            :: "r"(_m), "r"(_p) : "memory");                                   \
    }                                                                          \
} while (0)

__device__ __forceinline__ uint32_t pack_hl_f16(float v, float w, uint32_t& lo) {
    __half h0 = __float2half_rn(v);
    __half h1 = __float2half_rn(w);
    __half l0 = __float2half_rn(v - __half2float(h0));
    __half l1 = __float2half_rn(w - __half2float(h1));
    lo = (uint32_t)__half_as_ushort(l0) | ((uint32_t)__half_as_ushort(l1) << 16);
    return (uint32_t)__half_as_ushort(h0) | ((uint32_t)__half_as_ushort(h1) << 16);
}

// ---------------------------------------------------------------------------
__global__ void convert_x_kernel(const float* __restrict__ X,
                                 uint8_t* __restrict__ Xh,
                                 uint8_t* __restrict__ Xl) {
    const long gi = (long)(blockIdx.x * blockDim.x + threadIdx.x) * 8;
    const int row = (int)(gi / DD);
    const int k   = (int)(gi % DD);
    const float4 v0 = *(const float4*)(X + gi);
    const float4 v1 = *(const float4*)(X + gi + 4);
    uint32_t h[4], l[4];
    h[0] = pack_hl_f16(v0.x, v0.y, l[0]);
    h[1] = pack_hl_f16(v0.z, v0.w, l[1]);
    h[2] = pack_hl_f16(v1.x, v1.y, l[2]);
    h[3] = pack_hl_f16(v1.z, v1.w, l[3]);
    const size_t o = toff(row, k, A_PLANE);
    *(uint4*)(Xh + o) = make_uint4(h[0], h[1], h[2], h[3]);
    *(uint4*)(Xl + o) = make_uint4(l[0], l[1], l[2], l[3]);
}

// all 6 weight matrices in one launch: z = 0..5
__global__ void convert_wt_kernel(const float* __restrict__ qw1,
                                  const float* __restrict__ kw1,
                                  const float* __restrict__ vw1,
                                  const float* __restrict__ qw2,
                                  const float* __restrict__ kw2,
                                  const float* __restrict__ vw2,
                                  uint8_t* __restrict__ W1,
                                  uint8_t* __restrict__ W2) {
    __shared__ float tile[32][33];
    const int z = blockIdx.z;
    const float* W = (z == 0) ? qw1 : (z == 1) ? kw1 : (z == 2) ? vw1
                   : (z == 3) ? qw2 : (z == 4) ? kw2 : vw2;
    uint8_t* dst = (z < 3) ? (W1 + (size_t)z * SZ_W) : (W2 + (size_t)(z - 3) * SZ_W);

    const int bx = blockIdx.x * 32;
    const int by = blockIdx.y * 32;
    const int tx = threadIdx.x, ty = threadIdx.y;
    for (int r = ty; r < 32; r += 8)
        tile[r][tx] = W[(size_t)(by + r) * DD + bx + tx];
    __syncthreads();
    for (int r = ty; r < 32; r += 8) {
        const float v = tile[tx][r];
        const size_t o = toff(bx + r, by + tx, W_PLANE);
        *(__half*)(dst + o) = __float2half_rn(v);
    }
}

// ---------------------------------------------------------------------------
// fp16x2 GEMM (A split hi/lo, B single); producer/consumer mbarrier mainloop.
// ---------------------------------------------------------------------------
template<int LAYER>
__global__ void __launch_bounds__(512) mma_gemm_kernel(
    const uint8_t* __restrict__ Abh, const uint8_t* __restrict__ Abl,
    const uint8_t* __restrict__ Bb,
    const float* __restrict__ bias0, const float* __restrict__ bias1,
    const float* __restrict__ bias2,
    uint8_t* __restrict__ Ch, uint8_t* __restrict__ Cl)
{
    extern __shared__ char sm[];
    __shared__ uint64_t s_mbar[4];   // full0, full1, empty0, empty1
    const uint32_t smb = s2u(sm);
    const uint32_t mb0 = s2u(&s_mbar[0]);

    const int t    = threadIdx.x;
    const int warp = t >> 5;
    const int lane = t & 31;
    const int wm   = warp & 7;
    const int wn   = warp >> 3;
    const int n0   = blockIdx.x * 128;
    const int m0   = blockIdx.y * 256;
    const int z    = blockIdx.z;

    const uint8_t* Ah = Abh + (LAYER == 2 ? (size_t)z * SZ_X : 0);
    const uint8_t* Al = Abl + (LAYER == 2 ? (size_t)z * SZ_X : 0);
    const uint8_t* Bp = Bb + (size_t)z * SZ_W;
    const float* bias = (z == 0) ? bias0 : (z == 1) ? bias1 : bias2;

    if (t == 0) {
        MB_INIT(mb0, 1);  MB_INIT(mb0 + 8, 1);
        MB_INIT(mb0 + 16, 16);  MB_INIT(mb0 + 24, 16);
    }
    __syncthreads();

    auto load_chunk = [&](int c, int s) {
        const uint32_t sb = smb + s * STAGE;
        const uint32_t mb = mb0 + s * 8;
        MB_EXPECT(mb, STAGE);
        BULK_G2S(sb,          Ah + (size_t)c * A_PLANE + (size_t)m0 * 128, 32768, mb);
        BULK_G2S(sb + STG_AL, Al + (size_t)c * A_PLANE + (size_t)m0 * 128, 32768, mb);
        BULK_G2S(sb + STG_B,  Bp + (size_t)c * W_PLANE + (size_t)n0 * 128, 16384, mb);
    };

    const int l15   = lane & 15;
    const int uA    = lane >> 4;
    const int q3    = lane >> 3;
    const int brl   = lane & 7;
    const int brow  = (q3 < 2) ? brl : (8 + brl);
    const int uB    = q3 & 1;

    float acc[2][8][4];
    #pragma unroll
    for (int i = 0; i < 2; i++)
        #pragma unroll
        for (int j = 0; j < 8; j++)
            #pragma unroll
            for (int r = 0; r < 4; r++) acc[i][j][r] = 0.f;

    if (t == 0) load_chunk(0, 0);
    int pf[2] = {0, 0}, pe[2] = {0, 0};

    for (int c = 0; c < NCH; ++c) {
        const int s = c & 1;
        if (c + 1 < NCH && t == 0) {
            if (c >= 1) { MB_WAIT(mb0 + 16 + (s ^ 1) * 8, pe[s ^ 1]); pe[s ^ 1] ^= 1; }
            load_chunk(c + 1, s ^ 1);
        }
        MB_WAIT(mb0 + s * 8, pf[s]);
        pf[s] ^= 1;

        const uint32_t sb = smb + s * STAGE;
        #pragma unroll
        for (int k16 = 0; k16 < 64; k16 += 16) {
            uint32_t ah[2][4], al[2][4];
            #pragma unroll
            for (int mt = 0; mt < 2; mt++) {
                const int row = wm * 32 + mt * 16 + l15;
                const int u   = ((k16 >> 3) + uA) ^ (row & 7);
                const uint32_t ao = (uint32_t)(row * 128 + (u << 4));
                ldsm_x4(ah[mt], sb + ao);
                ldsm_x4(al[mt], sb + STG_AL + ao);
            }
            #pragma unroll
            for (int p = 0; p < 4; p++) {
                const int row = wn * 64 + p * 16 + brow;
                const int u   = ((k16 >> 3) + uB) ^ (row & 7);
                const uint32_t bo = (uint32_t)(row * 128 + (u << 4));
                uint32_t rh[4];
                ldsm_x4(rh, sb + STG_B + bo);
                #pragma unroll
                for (int h = 0; h < 2; h++) {
                    const int nt = 2 * p + h;
                    #pragma unroll
                    for (int mt = 0; mt < 2; mt++) {
                        mma_f16(acc[mt][nt], ah[mt], rh + 2 * h);
                        mma_f16(acc[mt][nt], al[mt], rh + 2 * h);
                    }
                }
            }
        }
        if (lane == 0) MB_ARRIVE(mb0 + 16 + s * 8);
    }

    const int gid = lane >> 2;
    const int qid = lane & 3;
    #pragma unroll
    for (int mt = 0; mt < 2; mt++) {
        #pragma unroll
        for (int nt = 0; nt < 8; nt++) {
            const int col = n0 + wn * 64 + nt * 8 + qid * 2;
            const float b0 = bias[col], b1 = bias[col + 1];
            #pragma unroll
            for (int half = 0; half < 2; half++) {
                const int row = m0 + wm * 32 + mt * 16 + gid + half * 8;
                float v0 = acc[mt][nt][half * 2]     + b0;
                float v1 = acc[mt][nt][half * 2 + 1] + b1;
                if (LAYER == 1) { v0 = gelu_exact(v0); v1 = gelu_exact(v1); }
                uint32_t lo;
                const uint32_t hi = pack_hl_f16(v0, v1, lo);
                if (LAYER == 1) {
                    const size_t o = (size_t)z * SZ_X + toff(row, col, A_PLANE);
                    *(uint32_t*)(Ch + o) = hi;
                    *(uint32_t*)(Cl + o) = lo;
                } else {
                    const size_t o = (size_t)z * SLOT + PAD_B + toff(row, col, A_PLANE);
                    *(uint32_t*)(Ch + o) = hi;
                    if (z == 0) *(uint32_t*)(Cl + o) = lo;   // only Q needs lo
                }
            }
        }
    }
}

// ---------------------------------------------------------------------------
// Banded attention + fused LayerNorm. Phase 1 & 2 fully mbarrier-pipelined.
// mbar map: 0/8 p1full, 16/24 p2full, 32/40 p1empty(8), 48/56 p2empty(8)
// ---------------------------------------------------------------------------
__global__ void __launch_bounds__(256) attn_kernel(
    const uint8_t* __restrict__ Qh, const uint8_t* __restrict__ Ql,
    const uint8_t* __restrict__ Kh, const uint8_t* __restrict__ Vh,
    const float* __restrict__ lnw, const float* __restrict__ lnb,
    float* __restrict__ out)
{
    extern __shared__ char smc[];
    __shared__ uint64_t s_mb[8];
    const uint32_t smb = s2u(smc);
    const uint32_t smA = smb + AT_A;
    float* Ysh = (float*)(smc + AT_Y);
    const uint32_t mb = s2u(&s_mb[0]);

    const int t    = threadIdx.x;
    const int warp = t >> 5;
    const int lane = t & 31;
    const int wm   = warp >> 2;
    const int wn   = warp & 3;
    const int gid  = lane >> 2;
    const int qid  = lane & 3;

    const int bx = blockIdx.x;
    const int b  = bx >> 7;
    const int i0 = (bx & 127) * TQ;
    const long base = (long)b * 4096;
    const long gq   = base + i0;
    const long gk   = base + i0 - 256;
    const int jb = i0 - 256;

    const int l15  = lane & 15;
    const int uA   = lane >> 4;
    const int q3   = lane >> 3;
    const int brl  = lane & 7;
    const int brow = (q3 < 2) ? brl : (8 + brl);
    const int uB   = q3 & 1;

    if (t == 0) {
        MB_INIT(mb, 1); MB_INIT(mb + 8, 1);
        MB_INIT(mb + 16, 1); MB_INIT(mb + 24, 1);
        MB_INIT(mb + 32, 8); MB_INIT(mb + 40, 8);
        MB_INIT(mb + 48, 8); MB_INIT(mb + 56, 8);
    }
    __syncthreads();

    // =================== phase 1: S = mask(Q @ K^T) ===================
    auto p1_load = [&](int c, int s) {
        const uint32_t sb = smA + s * P1_STG;
        const uint32_t m1 = mb + s * 8;
        MB_EXPECT(m1, 45056);
        BULK_G2S(sb,         Kh + ((long)c * A_PLANE + gk * 128), 36864, m1);
        BULK_G2S(sb + AT_QH, Qh + ((long)c * A_PLANE + gq * 128), 4096, m1);
        BULK_G2S(sb + AT_QL, Ql + ((long)c * A_PLANE + gq * 128), 4096, m1);
    };

    float acc[9][4];
    #pragma unroll
    for (int n = 0; n < 9; n++)
        #pragma unroll
        for (int r = 0; r < 4; r++) acc[n][r] = 0.f;

    if (t == 0) { p1_load(0, 0); p1_load(1, 1); }
    int pf1[2] = {0, 0}, pe1[2] = {0, 0};

    for (int c = 0; c < NCH; ++c) {
        const int s = c & 1;
        MB_WAIT(mb + s * 8, pf1[s]);
        pf1[s] ^= 1;

        const uint32_t sb = smA + s * P1_STG;
        #pragma unroll
        for (int k16 = 0; k16 < 64; k16 += 16) {
            uint32_t ah[4], al[4];
            {
                const int row = wm * 16 + l15;
                const int u   = ((k16 >> 3) + uA) ^ (row & 7);
                const uint32_t ao = (uint32_t)(row * 128 + (u << 4));
                ldsm_x4(ah, sb + AT_QH + ao);
                ldsm_x4(al, sb + AT_QL + ao);
            }
            uint32_t bh[9][2];
            #pragma unroll
            for (int p = 0; p < 4; p++) {
                const int row = wn * 72 + p * 16 + brow;
                const int u   = ((k16 >> 3) + uB) ^ (row & 7);
                const uint32_t bo = (uint32_t)(row * 128 + (u << 4));
                uint32_t r4[4];
                ldsm_x4(r4, sb + bo);
                bh[2*p][0] = r4[0]; bh[2*p][1] = r4[1];
                bh[2*p+1][0] = r4[2]; bh[2*p+1][1] = r4[3];
            }
            {
                const int row = wn * 72 + 64 + brl;
                const int u   = ((k16 >> 3) + ((lane >> 3) & 1)) ^ (row & 7);
                const uint32_t bo = (uint32_t)(row * 128 + (u << 4));
                ldsm_x2(bh[8], sb + bo);
            }
            #pragma unroll
            for (int nt = 0; nt < 9; nt++) {
                mma_f16(acc[nt], ah, bh[nt]);
                mma_f16(acc[nt], al, bh[nt]);
            }
        }
        if (lane == 0) MB_ARRIVE(mb + 32 + s * 8);
        if (t == 0 && c + 2 < NCH) {
            MB_WAIT(mb + 32 + s * 8, pe1[s]); pe1[s] ^= 1;
            p1_load(c + 2, s);
        }
    }

    // mask + scale + split hi/lo into S smem
    #pragma unroll
    for (int nt = 0; nt < 9; nt++) {
        const int jw0 = wn * 72 + nt * 8 + qid * 2;
        #pragma unroll
        for (int half = 0; half < 2; half++) {
            const int ti = wm * 16 + gid + half * 8;
            float v0 = acc[nt][half * 2];
            float v1 = acc[nt][half * 2 + 1];
            const bool ok0 = (jb + jw0     >= 0) && (jw0     > ti) && (jw0     <= ti + 256);
            const bool ok1 = (jb + jw0 + 1 >= 0) && (jw0 + 1 > ti) && (jw0 + 1 <= ti + 256);
            v0 = ok0 ? v0 * INV_SCALE : 0.f;
            v1 = ok1 ? v1 * INV_SCALE : 0.f;
            uint32_t lo;
            const uint32_t hi = pack_hl_f16(v0, v1, lo);
            const uint32_t so = (uint32_t)(ti * SSTR + jw0) * 2;
            *(uint32_t*)(smc + AT_SH + so) = hi;
            *(uint32_t*)(smc + AT_SL + so) = lo;
        }
    }
    __syncthreads();

    // =================== phase 2: Y = S @ V ===================
    auto p2_load = [&](int iter, int s) {
        const int dc = iter / 9;
        const int js = iter % 9;
        const long r0 = gk + js * 32;
        const uint32_t sb = smA + s * AT_P2S;
        const uint32_t m2 = mb + 16 + s * 8;
        MB_EXPECT(m2, 16384);
        #pragma unroll
        for (int q = 0; q < 4; q++) {
            const int cv = dc * 4 + q;
            BULK_G2S(sb + q * 4096, Vh + ((long)cv * A_PLANE + r0 * 128), 4096, m2);
        }
    };

    float acc2[8][4];
    #pragma unroll
    for (int n = 0; n < 8; n++)
        #pragma unroll
        for (int r = 0; r < 4; r++) acc2[n][r] = 0.f;

    if (t == 0) { p2_load(0, 0); p2_load(1, 1); }
    int pf2[2] = {0, 0}, pe2[2] = {0, 0};

    for (int iter = 0; iter < 27; ++iter) {
        const int s = iter & 1;
        MB_WAIT(mb + 16 + s * 8, pf2[s]);
        pf2[s] ^= 1;

        const int js = (iter % 9) * 32;
        const uint32_t sb = smA + s * AT_P2S;
        #pragma unroll
        for (int k16 = 0; k16 < 32; k16 += 16) {
            uint32_t ah[4], al[4];
            const uint32_t ao = (uint32_t)((wm * 16 + l15) * SSTR + js + k16 + uA * 8) * 2;
            ldsm_x4(ah, smb + AT_SH + ao);
            ldsm_x4(al, smb + AT_SL + ao);

            uint32_t bh[8][2];
            #pragma unroll
            for (int p = 0; p < 4; p++) {
                const int row = k16 + l15;
                const int u   = (2 * p + uA) ^ (row & 7);
                const uint32_t bo = (uint32_t)(wn * 4096 + row * 128 + (u << 4));
                uint32_t r4[4];
                ldsm_x4_t(r4, sb + bo);
                bh[2*p][0] = r4[0]; bh[2*p][1] = r4[1];
                bh[2*p+1][0] = r4[2]; bh[2*p+1][1] = r4[3];
            }
            #pragma unroll
            for (int nt = 0; nt < 8; nt++) {
                mma_f16(acc2[nt], ah, bh[nt]);
                mma_f16(acc2[nt], al, bh[nt]);
            }
        }
        if (lane == 0) MB_ARRIVE(mb + 48 + s * 8);

        if ((iter % 9) == 8) {
            const int dc = (iter / 9) * 256;
            #pragma unroll
            for (int nt = 0; nt < 8; nt++) {
                const int col = dc + wn * 64 + nt * 8 + qid * 2;
                #pragma unroll
                for (int half = 0; half < 2; half++) {
                    const int row = wm * 16 + gid + half * 8;
                    *(float2*)&Ysh[row * DD + col] =
                        make_float2(acc2[nt][half * 2], acc2[nt][half * 2 + 1]);
                }
            }
            #pragma unroll
            for (int n = 0; n < 8; n++)
                #pragma unroll
                for (int r = 0; r < 4; r++) acc2[n][r] = 0.f;
        }
        if (t == 0 && iter + 2 < 27) {
            MB_WAIT(mb + 48 + s * 8, pe2[s]); pe2[s] ^= 1;
            p2_load(iter + 2, s);
        }
    }
    __syncthreads();

    // =================== phase 3: fused LayerNorm ===================
    #pragma unroll
    for (int rr = 0; rr < 4; rr++) {
        const int row = warp * 4 + rr;
        float s = 0.f, ss = 0.f;
        #pragma unroll
        for (int c0 = 0; c0 < DD; c0 += 32) {
            const float y = Ysh[row * DD + c0 + lane];
            s += y; ss += y * y;
        }
        #pragma unroll
        for (int o = 16; o > 0; o >>= 1) {
            s  += __shfl_xor_sync(0xffffffffu, s,  o);
            ss += __shfl_xor_sync(0xffffffffu, ss, o);
        }
        const float mu   = s * (1.f / 768.f);
        const float var  = ss * (1.f / 768.f) - mu * mu;
        const float rstd = rsqrtf(var + 1e-5f);
        #pragma unroll
        for (int c0 = 0; c0 < DD; c0 += 32) {
            const int c = c0 + lane;
            const float y = Ysh[row * DD + c];
            out[(gq + row) * DD + c] = (y - mu) * rstd * lnw[c] + lnb[c];
        }
    }
}

// ---------------------------------------------------------------------------
extern "C" void kernel_launch(void* const* d_in, const int* in_sizes, int n_in,
                              void* d_out, int out_size)
{
    const float* x   = (const float*)d_in[0];
    const float* qw1 = (const float*)d_in[1];
    const float* qb1 = (const float*)d_in[2];
    const float* qw2 = (const float*)d_in[3];
    const float* qb2 = (const float*)d_in[4];
    const float* kw1 = (const float*)d_in[5];
    const float* kb1 = (const float*)d_in[6];
    const float* kw2 = (const float*)d_in[7];
    const float* kb2 = (const float*)d_in[8];
    const float* vw1 = (const float*)d_in[9];
    const float* vb1 = (const float*)d_in[10];
    const float* vw2 = (const float*)d_in[11];
    const float* vb2 = (const float*)d_in[12];
    const float* lnw = (const float*)d_in[13];
    const float* lnb = (const float*)d_in[14];
    float* out = (float*)d_out;

    uint8_t *Xh, *Xl, *Hh, *Hl, *W1, *W2, *QKVh, *QKVl;
    cudaGetSymbolAddress((void**)&Xh, g_Xh);
    cudaGetSymbolAddress((void**)&Xl, g_Xl);
    cudaGetSymbolAddress((void**)&Hh, g_Hh);
    cudaGetSymbolAddress((void**)&Hl, g_Hl);
    cudaGetSymbolAddress((void**)&W1, g_W1);
    cudaGetSymbolAddress((void**)&W2, g_W2);
    cudaGetSymbolAddress((void**)&QKVh, g_QKVh);
    cudaGetSymbolAddress((void**)&QKVl, g_QKVl);

    cudaFuncSetAttribute(mma_gemm_kernel<1>,
                         cudaFuncAttributeMaxDynamicSharedMemorySize, GEMM_SMEM);
    cudaFuncSetAttribute(mma_gemm_kernel<2>,
                         cudaFuncAttributeMaxDynamicSharedMemorySize, GEMM_SMEM);
    cudaFuncSetAttribute(attn_kernel,
                         cudaFuncAttributeMaxDynamicSharedMemorySize, ATTN_SMEM);

    convert_x_kernel<<<(MT * DD) / (256 * 8), 256>>>(x, Xh, Xl);

    const dim3 gw(24, 24, 6);
    const dim3 bw(32, 8);
    convert_wt_kernel<<<gw, bw>>>(qw1, kw1, vw1, qw2, kw2, vw2, W1, W2);

    const dim3 gg(DD / 128, MT / 256, 3);
    mma_gemm_kernel<1><<<gg, 512, GEMM_SMEM>>>(Xh, Xl, W1,
                                               qb1, kb1, vb1, Hh, Hl);
    mma_gemm_kernel<2><<<gg, 512, GEMM_SMEM>>>(Hh, Hl, W2,
                                               qb2, kb2, vb2, QKVh, QKVl);

    attn_kernel<<<MT / TQ, 256, ATTN_SMEM>>>(
        QKVh + PAD_B,               QKVl + PAD_B,
        QKVh + SLOT + PAD_B,
        QKVh + 2ull * SLOT + PAD_B,
        lnw, lnb, out);
}